// round 13
// baseline (speedup 1.0000x reference)
#include <cuda_runtime.h>
#include <cuda_bf16.h>
#include <math.h>
#include <stdint.h>

#define NN 50000
#define NE 800000
#define FIN 64
#define HH 128
#define LL 3
#define CC 4
#define KK 32
#define NOPS 7
#define NB 512
#define NOUT 10
#define BNG 400

// ------------------------- device scratch (no allocs) -------------------------
__device__ float g_gr[(LL+1)*NN*HH];
__device__ float g_xw[NN*HH];
__device__ float g_sum[NN*HH];
__device__ float g_nrm[NN*HH];
__device__ float g_att[NN*HH];
__device__ float g_s0[NN];
__device__ float g_s1[NN];
__device__ float g_dinv[NN];
__device__ float g_minv[NN];
__device__ int   g_deg[NN];
__device__ int   g_rowptr[NN+1];
__device__ int   g_cursor[NN];
__device__ int   g_csrsrc[NE];
__device__ int   g_bstart[NB+1];
__device__ float g_wmix[LL*CC*NOPS];
__device__ float g_h1[NB*2*HH];
__device__ float g_h2[NB*HH];
__device__ float g_scA[(LL+1)*HH];
__device__ float g_shA[(LL+1)*HH];
__device__ float g_sc1[2*HH];
__device__ float g_sh1[2*HH];
__device__ float g_sc2[HH];
__device__ float g_sh2[HH];
__device__ float g_part[2*BNG*HH];
__device__ float g_pooled[NB*8*HH];
__device__ int   g_cbn = 0;
__device__ int   g_c1 = 0;
__device__ int   g_c2 = 0;
__device__ unsigned short g_Whi[LL*NOPS*16384];
__device__ unsigned short g_Wlo[LL*NOPS*16384];
__device__ unsigned short g_W1hi[128*64];
__device__ unsigned short g_W1lo[128*64];

// ------------------------- PTX helpers (baseline ISA, sm_80+) -------------------------
__device__ __forceinline__ uint32_t smem_u32(const void* p){
  uint32_t a; asm("{ .reg .u64 t; cvta.to.shared.u64 t, %1; cvt.u32.u64 %0, t; }" : "=r"(a) : "l"(p));
  return a;
}
__device__ __forceinline__ void ldsm4(uint32_t &r0, uint32_t &r1, uint32_t &r2, uint32_t &r3, uint32_t addr){
  asm volatile("ldmatrix.sync.aligned.m8n8.x4.shared.b16 {%0,%1,%2,%3}, [%4];"
    : "=r"(r0), "=r"(r1), "=r"(r2), "=r"(r3) : "r"(addr));
}
__device__ __forceinline__ void mma16816(float* d, const uint32_t* a, const uint32_t* b){
  asm volatile("mma.sync.aligned.m16n8k16.row.col.f32.bf16.bf16.f32 "
    "{%0,%1,%2,%3}, {%4,%5,%6,%7}, {%8,%9}, {%0,%1,%2,%3};"
    : "+f"(d[0]), "+f"(d[1]), "+f"(d[2]), "+f"(d[3])
    : "r"(a[0]), "r"(a[1]), "r"(a[2]), "r"(a[3]), "r"(b[0]), "r"(b[1]));
}
__device__ __forceinline__ void cpa16(uint32_t saddr, const void* gaddr){
  asm volatile("cp.async.cg.shared.global [%0], [%1], 16;" :: "r"(saddr), "l"(gaddr));
}
#define CPA_COMMIT() asm volatile("cp.async.commit_group;" ::: "memory")
#define CPA_WAIT()   asm volatile("cp.async.wait_group 0;" ::: "memory")

// ------------------------- CSR build -------------------------
__global__ void k_zero_deg(){
  int i = blockIdx.x*blockDim.x + threadIdx.x;
  if (i < NN) g_deg[i] = 0;
}
__global__ void k_count(const int* __restrict__ dst){
  int e = blockIdx.x*blockDim.x + threadIdx.x;
  if (e < NE) atomicAdd(&g_deg[dst[e]], 1);
}
__global__ void k_scan(){
  __shared__ int sm[1024];
  const int CH = (NN + 1023)/1024;
  int t = threadIdx.x;
  int s = 0;
  for (int i=0;i<CH;i++){ int idx = t*CH+i; if (idx<NN) s += g_deg[idx]; }
  sm[t] = s; __syncthreads();
  for (int off=1; off<1024; off<<=1){
    int v = (t>=off) ? sm[t-off] : 0;
    __syncthreads();
    if (t>=off) sm[t] += v;
    __syncthreads();
  }
  int run = (t>0)? sm[t-1] : 0;
  for (int i=0;i<CH;i++){
    int idx=t*CH+i;
    if (idx<NN){
      g_rowptr[idx]=run;
      g_cursor[idx]=run;
      int d = g_deg[idx];
      run += d;
      float dc = (float)max(d, 1);
      g_dinv[idx] = rsqrtf(dc);
      g_minv[idx] = 1.f/dc;
    }
  }
  if (t==1023) g_rowptr[NN] = sm[1023];
}
__global__ void k_scatter(const int* __restrict__ src, const int* __restrict__ dst){
  int e = blockIdx.x*blockDim.x + threadIdx.x;
  if (e < NE){
    int slot = atomicAdd(&g_cursor[dst[e]], 1);
    g_csrsrc[slot] = src[e];
  }
}
__global__ void k_bstart(const int* __restrict__ batch){
  int i = blockIdx.x*blockDim.x + threadIdx.x;
  if (i >= NN) return;
  int b = batch[i];
  if (i == 0){ for (int bb=0; bb<=b; bb++) g_bstart[bb] = 0; }
  else { int p = batch[i-1]; for (int bb=p+1; bb<=b; bb++) g_bstart[bb] = i; }
  if (i == NN-1){ for (int bb=b+1; bb<=NB; bb++) g_bstart[bb] = NN; }
}
__global__ void k_prepw(const float* __restrict__ alphas){
  int g = threadIdx.x;
  if (g < 128){ g_scA[g] = 1.f; g_shA[g] = 0.f; }
  if (g < LL*CC){
    const float* a = alphas + g*NOPS;
    float mx = a[0];
    for (int o=1;o<NOPS;o++) mx = fmaxf(mx, a[o]);
    float e[NOPS]; float s = 0.f;
    for (int o=0;o<NOPS;o++){ e[o] = expf(a[o]-mx); s += e[o]; }
    for (int o=0;o<NOPS;o++) g_wmix[g*NOPS+o] = e[o]/s;
  }
}

// ------------------------- weight prep -------------------------
__global__ void k_wprep(const float* __restrict__ Wops){
  int idx = blockIdx.x*blockDim.x + threadIdx.x;
  if (idx >= LL*NOPS*16384) return;
  int lop = idx >> 14;
  int el  = idx & 16383;
  int l = lop / NOPS, o = lop % NOPS;
  int r = el >> 7;
  int h = el & 127;
  int c = r >> 5, k = r & 31;
  float w = Wops[(((size_t)(l*CC + c)*NOPS + o)*HH + h)*KK + k];
  __nv_bfloat16 hb = __float2bfloat16(w);
  float res = w - __bfloat162float(hb);
  __nv_bfloat16 lb = __float2bfloat16(res);
  g_Whi[(size_t)lop*16384 + r*128 + h] = __bfloat16_as_ushort(hb);
  g_Wlo[(size_t)lop*16384 + r*128 + h] = __bfloat16_as_ushort(lb);
}
__global__ void k_wprep1(const float* __restrict__ W){
  int idx = blockIdx.x*blockDim.x + threadIdx.x;
  if (idx >= 128*64) return;
  int r = idx >> 6, h = idx & 63;
  float w = W[h*128 + r];
  __nv_bfloat16 hb = __float2bfloat16(w);
  float res = w - __bfloat162float(hb);
  __nv_bfloat16 lb = __float2bfloat16(res);
  g_W1hi[r*64+h] = __bfloat16_as_ushort(hb);
  g_W1lo[r*64+h] = __bfloat16_as_ushort(lb);
}

// ------------------------- lin1 + ELU via warp MMA -------------------------
#define PADK1 72
#define L1_AHI 0
#define L1_ALO (64*PADK1*2)
#define L1_WHI (2*64*PADK1*2)
#define L1_WLO (L1_WHI + 128*PADK1*2)
#define L1_BB  (L1_WLO + 128*PADK1*2)
#define SMEM_L1 (L1_BB + 512)

__global__ void __launch_bounds__(256,3) k_lin1_mma(const float* __restrict__ x,
    const float* __restrict__ bias){
  extern __shared__ char smc[];
  uint32_t sbase = smem_u32(smc);
  float* s_b1 = (float*)(smc + L1_BB);
  int tid = threadIdx.x;
  int lane = tid & 31, w = tid >> 5;
  int wr = w & 3, wc = w >> 2;
  int g = lane >> 2, tig = lane & 3;
  int n0 = blockIdx.x * 64;
  if (tid < 128) s_b1[tid] = bias[tid];

  #pragma unroll 1
  for (int it=0; it<8; it++){
    int wi = it*256 + tid;
    int r = wi >> 5;
    int h0 = (wi & 31)*2;
    int n = n0 + r;
    float vx=0.f, vy=0.f;
    if (n < NN){
      float2 a = *(const float2*)(x + (size_t)n*FIN + h0);
      vx=a.x; vy=a.y;
    }
    __nv_bfloat16 hx = __float2bfloat16(vx);
    __nv_bfloat16 hy = __float2bfloat16(vy);
    __nv_bfloat16 lx = __float2bfloat16(vx - __bfloat162float(hx));
    __nv_bfloat16 ly = __float2bfloat16(vy - __bfloat162float(hy));
    uint32_t off = (uint32_t)(r*PADK1 + h0)*2;
    *(uint32_t*)(smc + L1_AHI + off) = (uint32_t)__bfloat16_as_ushort(hx) | ((uint32_t)__bfloat16_as_ushort(hy)<<16);
    *(uint32_t*)(smc + L1_ALO + off) = (uint32_t)__bfloat16_as_ushort(lx) | ((uint32_t)__bfloat16_as_ushort(ly)<<16);
  }
  {
    const uint4* srcH = (const uint4*)g_W1hi;
    const uint4* srcL = (const uint4*)g_W1lo;
    #pragma unroll
    for (int it=0; it<4; it++){
      int i = it*256 + tid;
      int row = i >> 3, q = i & 7;
      uint32_t off = (uint32_t)(row*PADK1 + q*8)*2;
      *(uint4*)(smc + L1_WHI + off) = srcH[i];
      *(uint4*)(smc + L1_WLO + off) = srcL[i];
    }
  }
  __syncthreads();

  int a_off = ((lane&7) + ((lane>>3)&1)*8)*PADK1 + (lane>>4)*8;
  int b_off = (((lane>>4)&1)*8 + (lane&7))*PADK1 + ((lane>>3)&1)*8;
  uint32_t AbH = sbase + L1_AHI + (uint32_t)(wr*16*PADK1 + a_off)*2;
  uint32_t AbL = sbase + L1_ALO + (uint32_t)(wr*16*PADK1 + a_off)*2;
  uint32_t WbH = sbase + L1_WHI + (uint32_t)(wc*64*PADK1 + b_off)*2;
  uint32_t WbL = sbase + L1_WLO + (uint32_t)(wc*64*PADK1 + b_off)*2;

  float acc[8][4];
  #pragma unroll
  for (int f=0;f<8;f++){ acc[f][0]=0.f; acc[f][1]=0.f; acc[f][2]=0.f; acc[f][3]=0.f; }
  #pragma unroll
  for (int ks=0; ks<4; ks++){
    uint32_t k0b = (uint32_t)(ks*16)*2;
    uint32_t ah[4], al[4];
    ldsm4(ah[0],ah[1],ah[2],ah[3], AbH + k0b);
    ldsm4(al[0],al[1],al[2],al[3], AbL + k0b);
    #pragma unroll
    for (int nf=0; nf<4; nf++){
      uint32_t bh[4], bl[4];
      uint32_t woff = (uint32_t)(nf*16*PADK1)*2 + k0b;
      ldsm4(bh[0],bh[1],bh[2],bh[3], WbH + woff);
      ldsm4(bl[0],bl[1],bl[2],bl[3], WbL + woff);
      mma16816(acc[2*nf],   ah, bh);
      mma16816(acc[2*nf],   ah, bl);
      mma16816(acc[2*nf],   al, bh);
      mma16816(acc[2*nf+1], ah, bh+2);
      mma16816(acc[2*nf+1], ah, bl+2);
      mma16816(acc[2*nf+1], al, bh+2);
    }
  }
  int rA = n0 + wr*16 + g;
  int rB = rA + 8;
  #pragma unroll
  for (int f=0; f<8; f++){
    int col = wc*64 + f*8 + 2*tig;
    float b0 = s_b1[col], b1 = s_b1[col+1];
    float t0 = acc[f][0]+b0, t1 = acc[f][1]+b1;
    float t2 = acc[f][2]+b0, t3 = acc[f][3]+b1;
    t0 = t0>0.f ? t0 : expm1f(t0);
    t1 = t1>0.f ? t1 : expm1f(t1);
    t2 = t2>0.f ? t2 : expm1f(t2);
    t3 = t3>0.f ? t3 : expm1f(t3);
    if (rA < NN) *(float2*)&g_gr[(size_t)rA*HH + col] = make_float2(t0, t1);
    if (rB < NN) *(float2*)&g_gr[(size_t)rB*HH + col] = make_float2(t2, t3);
  }
}

// ------------------------- per-layer node prep (lazy BN affine + lazy vn) -------------------------
__global__ void k_nodeA(const int* __restrict__ batch, const float* __restrict__ atta,
                        const float* __restrict__ vn0, int l){
  int w = (blockIdx.x*blockDim.x + threadIdx.x) >> 5;
  int lane = threadIdx.x & 31;
  if (w >= NN) return;
  int b = batch[w];
  float4 xv = ((const float4*)(g_gr + (size_t)l*NN*HH))[w*32 + lane];
  float4 sc = ((const float4*)(g_scA + l*HH))[lane];
  float4 sh = ((const float4*)(g_shA + l*HH))[lane];
  xv.x = xv.x*sc.x+sh.x; xv.y = xv.y*sc.y+sh.y; xv.z = xv.z*sc.z+sh.z; xv.w = xv.w*sc.w+sh.w;
  float4 vv;
  if (l == 0){
    vv = ((const float4*)vn0)[lane];
  } else {
    float4 h2 = ((const float4*)g_h2)[b*32 + lane];
    float4 c2 = ((const float4*)g_sc2)[lane];
    float4 d2 = ((const float4*)g_sh2)[lane];
    vv.x = fmaxf(h2.x*c2.x+d2.x, 0.f);
    vv.y = fmaxf(h2.y*c2.y+d2.y, 0.f);
    vv.z = fmaxf(h2.z*c2.z+d2.z, 0.f);
    vv.w = fmaxf(h2.w*c2.w+d2.w, 0.f);
  }
  xv.x += vv.x; xv.y += vv.y; xv.z += vv.z; xv.w += vv.w;
  ((float4*)g_xw)[w*32 + lane] = xv;
  float4 a0 = ((const float4*)(atta + l*2*HH))[lane];
  float4 a1 = ((const float4*)(atta + l*2*HH + HH))[lane];
  float s0 = xv.x*a0.x + xv.y*a0.y + xv.z*a0.z + xv.w*a0.w;
  float s1 = xv.x*a1.x + xv.y*a1.y + xv.z*a1.z + xv.w*a1.w;
  #pragma unroll
  for (int off=16; off; off>>=1){
    s0 += __shfl_xor_sync(0xffffffffu, s0, off);
    s1 += __shfl_xor_sync(0xffffffffu, s1, off);
  }
  if (lane==0){ g_s0[w]=s0; g_s1[w]=s1; }
}

// ------------------------- fused attention + aggregation (warp per node) -------------------------
__global__ void k_edge(){
  int w = (blockIdx.x*blockDim.x + threadIdx.x) >> 5;
  int lane = threadIdx.x & 31;
  if (w >= NN) return;
  int s = g_rowptr[w], e = g_rowptr[w+1];
  float s1v = g_s1[w];
  float dv = g_dinv[w];
  float ss = 0.f;
  for (int j=s+lane; j<e; j+=32){
    float ev = g_s0[g_csrsrc[j]] + s1v;
    ev = ev>0.f ? ev : 0.2f*ev;
    ss += expf(ev);
  }
  #pragma unroll
  for (int off=16; off; off>>=1) ss += __shfl_xor_sync(0xffffffffu, ss, off);
  float sinv = 1.f/(ss + 1e-16f);
  float4 a_s = make_float4(0.f,0.f,0.f,0.f);
  float4 a_n = a_s, a_a = a_s;
  int j = s;
  for (; j+4<=e; j+=4){
    int sn0=g_csrsrc[j], sn1=g_csrsrc[j+1], sn2=g_csrsrc[j+2], sn3=g_csrsrc[j+3];
    float4 x0 = ((const float4*)g_xw)[sn0*32 + lane];
    float4 x1 = ((const float4*)g_xw)[sn1*32 + lane];
    float4 x2 = ((const float4*)g_xw)[sn2*32 + lane];
    float4 x3 = ((const float4*)g_xw)[sn3*32 + lane];
    float e0=g_s0[sn0]+s1v, e1=g_s0[sn1]+s1v, e2=g_s0[sn2]+s1v, e3=g_s0[sn3]+s1v;
    e0 = e0>0.f? e0:0.2f*e0; e1 = e1>0.f? e1:0.2f*e1;
    e2 = e2>0.f? e2:0.2f*e2; e3 = e3>0.f? e3:0.2f*e3;
    float c0=expf(e0)*sinv, c1=expf(e1)*sinv, c2=expf(e2)*sinv, c3=expf(e3)*sinv;
    float w0=g_dinv[sn0]*dv, w1=g_dinv[sn1]*dv, w2=g_dinv[sn2]*dv, w3=g_dinv[sn3]*dv;
    a_s.x+=x0.x+x1.x+x2.x+x3.x; a_s.y+=x0.y+x1.y+x2.y+x3.y;
    a_s.z+=x0.z+x1.z+x2.z+x3.z; a_s.w+=x0.w+x1.w+x2.w+x3.w;
    a_n.x+=w0*x0.x+w1*x1.x+w2*x2.x+w3*x3.x; a_n.y+=w0*x0.y+w1*x1.y+w2*x2.y+w3*x3.y;
    a_n.z+=w0*x0.z+w1*x1.z+w2*x2.z+w3*x3.z; a_n.w+=w0*x0.w+w1*x1.w+w2*x2.w+w3*x3.w;
    a_a.x+=c0*x0.x+c1*x1.x+c2*x2.x+c3*x3.x; a_a.y+=c0*x0.y+c1*x1.y+c2*x2.y+c3*x3.y;
    a_a.z+=c0*x0.z+c1*x1.z+c2*x2.z+c3*x3.z; a_a.w+=c0*x0.w+c1*x1.w+c2*x2.w+c3*x3.w;
  }
  for (; j<e; j++){
    int sn = g_csrsrc[j];
    float ev = g_s0[sn] + s1v;
    ev = ev>0.f ? ev : 0.2f*ev;
    float ca = expf(ev) * sinv;
    float nw = g_dinv[sn]*dv;
    float4 xv = ((const float4*)g_xw)[sn*32 + lane];
    a_s.x+=xv.x;      a_s.y+=xv.y;      a_s.z+=xv.z;      a_s.w+=xv.w;
    a_n.x+=nw*xv.x;   a_n.y+=nw*xv.y;   a_n.z+=nw*xv.z;   a_n.w+=nw*xv.w;
    a_a.x+=ca*xv.x;   a_a.y+=ca*xv.y;   a_a.z+=ca*xv.z;   a_a.w+=ca*xv.w;
  }
  ((float4*)g_sum)[w*32+lane]=a_s;
  ((float4*)g_nrm)[w*32+lane]=a_n;
  ((float4*)g_att)[w*32+lane]=a_a;
}

// ------------------------- warp-MMA mixed-op GEMM + LN + DARTS mix -------------------------
// 512 threads, 16 warps in 4x4 grid; warp = 16 rows x 32 cols. 32 accum regs/thread.
#define MT 64
#define PADK 136
#define SM_AHI 0
#define SM_ALO (MT*PADK*2)
#define SM_WHI (2*MT*PADK*2)
#define SM_WLO (SM_WHI + 128*PADK*2)
#define SM_BB  (SM_WLO + 128*PADK*2)
#define SM_LG  (SM_BB+512)
#define SM_LB  (SM_LG+512)
#define SMEM_MIX (SM_LB+512)

__constant__ int c_opseq[7] = {0,5,1,2,3,4,6};
__constant__ int c_asel[7]  = {0,0,1,2,3,4,5};

__global__ void __launch_bounds__(512,1) k_mix_mma(int l,
    const float* __restrict__ bops, const float* __restrict__ lng, const float* __restrict__ lnb){
  extern __shared__ char smc[];
  uint32_t sbase = smem_u32(smc);
  float* s_bb = (float*)(smc + SM_BB);
  float* s_lg = (float*)(smc + SM_LG);
  float* s_lb = (float*)(smc + SM_LB);
  int tid = threadIdx.x;
  int lane = tid & 31, w = tid >> 5;        // 16 warps
  int wr = w & 3, wc = w >> 2;              // 4 row-groups x 4 col-groups
  int g = lane >> 2, tig = lane & 3;
  int n0 = blockIdx.x * MT;
  if (tid < 128){ s_lg[tid] = lng[l*128+tid]; s_lb[tid] = lnb[l*128+tid]; }

  int a_off = ((lane&7) + ((lane>>3)&1)*8)*PADK + (lane>>4)*8;
  int b_off = (((lane>>4)&1)*8 + (lane&7))*PADK + ((lane>>3)&1)*8;
  uint32_t AbH = sbase + SM_AHI + (uint32_t)(wr*16*PADK + a_off)*2;
  uint32_t AbL = sbase + SM_ALO + (uint32_t)(wr*16*PADK + a_off)*2;
  uint32_t WbH = sbase + SM_WHI + (uint32_t)(wc*32*PADK)*2 + (uint32_t)b_off*2;
  uint32_t WbL = sbase + SM_WLO + (uint32_t)(wc*32*PADK)*2 + (uint32_t)b_off*2;

  float mix[4][4];
  #pragma unroll
  for (int f=0;f<4;f++){ mix[f][0]=0.f; mix[f][1]=0.f; mix[f][2]=0.f; mix[f][3]=0.f; }

  int prevA = -1;
  for (int oi=0; oi<7; oi++){
    int o = c_opseq[oi], asel = c_asel[oi];
    __syncthreads();
    // W tiles via cp.async — overlaps with A-build below
    {
      const uint4* srcH = (const uint4*)(g_Whi + (size_t)(l*NOPS+o)*16384);
      const uint4* srcL = (const uint4*)(g_Wlo + (size_t)(l*NOPS+o)*16384);
      #pragma unroll
      for (int it=0; it<4; it++){
        int i = it*512 + tid;
        int row = i >> 4, q = i & 15;
        uint32_t off = (uint32_t)(row*PADK + q*8)*2;
        cpa16(sbase + SM_WHI + off, srcH + i);
        cpa16(sbase + SM_WLO + off, srcL + i);
      }
      CPA_COMMIT();
    }
    if (asel != prevA){
      prevA = asel;
      #pragma unroll 1
      for (int it=0; it<8; it++){
        int wi = it*512 + tid;
        int r = wi >> 6;
        int h0 = (wi & 63)*2;
        int n = n0 + r;
        float vx=0.f, vy=0.f;
        if (n < NN){
          size_t base = (size_t)n*HH + h0;
          if (asel==0){ float2 a = *(const float2*)(g_nrm+base); vx=a.x; vy=a.y; }
          else if (asel==1){ float2 a=*(const float2*)(g_xw+base); float2 bq=*(const float2*)(g_sum+base); vx=a.x+bq.x; vy=a.y+bq.y; }
          else if (asel==2){ float2 a=*(const float2*)(g_att+base); vx=a.x; vy=a.y; }
          else if (asel==3){ float2 a=*(const float2*)(g_xw+base); float2 bq=*(const float2*)(g_sum+base); float m=g_minv[n]; vx=a.x+bq.x*m; vy=a.y+bq.y*m; }
          else if (asel==4){ float2 bq=*(const float2*)(g_sum+base); float m=g_minv[n]; vx=bq.x*m; vy=bq.y*m; }
          else { float2 a=*(const float2*)(g_xw+base); vx=a.x; vy=a.y; }
        }
        __nv_bfloat16 hx = __float2bfloat16(vx);
        __nv_bfloat16 hy = __float2bfloat16(vy);
        __nv_bfloat16 lx = __float2bfloat16(vx - __bfloat162float(hx));
        __nv_bfloat16 ly = __float2bfloat16(vy - __bfloat162float(hy));
        uint32_t off = (uint32_t)(r*PADK + h0)*2;
        *(uint32_t*)(smc + SM_AHI + off) = (uint32_t)__bfloat16_as_ushort(hx) | ((uint32_t)__bfloat16_as_ushort(hy)<<16);
        *(uint32_t*)(smc + SM_ALO + off) = (uint32_t)__bfloat16_as_ushort(lx) | ((uint32_t)__bfloat16_as_ushort(ly)<<16);
      }
    }
    if (tid < 128){
      int c = tid>>5, k = tid&31;
      s_bb[tid] = bops[((size_t)(l*CC + c)*NOPS + o)*KK + k];
    }
    CPA_WAIT();
    __syncthreads();

    float acc[4][4];
    #pragma unroll
    for (int f=0;f<4;f++){ acc[f][0]=0.f; acc[f][1]=0.f; acc[f][2]=0.f; acc[f][3]=0.f; }
    #pragma unroll 1
    for (int ks=0; ks<8; ks++){
      uint32_t k0b = (uint32_t)(ks*16)*2;
      uint32_t ah[4], al[4];
      ldsm4(ah[0],ah[1],ah[2],ah[3], AbH + k0b);
      ldsm4(al[0],al[1],al[2],al[3], AbL + k0b);
      #pragma unroll
      for (int nf=0; nf<2; nf++){
        uint32_t bh[4], bl[4];
        uint32_t woff = (uint32_t)(nf*16*PADK)*2 + k0b;
        ldsm4(bh[0],bh[1],bh[2],bh[3], WbH + woff);
        ldsm4(bl[0],bl[1],bl[2],bl[3], WbL + woff);
        mma16816(acc[2*nf],   ah, bh);
        mma16816(acc[2*nf],   ah, bl);
        mma16816(acc[2*nf],   al, bh);
        mma16816(acc[2*nf+1], ah, bh+2);
        mma16816(acc[2*nf+1], ah, bl+2);
        mma16816(acc[2*nf+1], al, bh+2);
      }
    }
    // epilogue: bias + LN(32) per (row, c=wc) + affine + mix
    {
      int c = wc;
      float tv[4][4];
      float sA=0.f, sqA=0.f, sB=0.f, sqB=0.f;
      #pragma unroll
      for (int fi=0; fi<4; fi++){
        int col0 = wc*32 + fi*8 + 2*tig;
        float b0 = s_bb[col0], b1 = s_bb[col0+1];
        float t0 = acc[fi][0]+b0, t1 = acc[fi][1]+b1;
        float t2 = acc[fi][2]+b0, t3 = acc[fi][3]+b1;
        tv[fi][0]=t0; tv[fi][1]=t1; tv[fi][2]=t2; tv[fi][3]=t3;
        sA += t0+t1; sqA += t0*t0+t1*t1;
        sB += t2+t3; sqB += t2*t2+t3*t3;
      }
      sA += __shfl_xor_sync(0xffffffffu, sA, 1);  sqA += __shfl_xor_sync(0xffffffffu, sqA, 1);
      sB += __shfl_xor_sync(0xffffffffu, sB, 1);  sqB += __shfl_xor_sync(0xffffffffu, sqB, 1);
      sA += __shfl_xor_sync(0xffffffffu, sA, 2);  sqA += __shfl_xor_sync(0xffffffffu, sqA, 2);
      sB += __shfl_xor_sync(0xffffffffu, sB, 2);  sqB += __shfl_xor_sync(0xffffffffu, sqB, 2);
      float mA = sA*(1.f/32.f), vA = sqA*(1.f/32.f) - mA*mA;
      float mB = sB*(1.f/32.f), vB = sqB*(1.f/32.f) - mB*mB;
      float rA2 = rsqrtf(vA + 1e-5f), rB2 = rsqrtf(vB + 1e-5f);
      float wv = g_wmix[(l*CC + c)*NOPS + o];
      #pragma unroll
      for (int fi=0; fi<4; fi++){
        int col0 = wc*32 + fi*8 + 2*tig;
        float lg0=s_lg[col0], lg1=s_lg[col0+1], lb0=s_lb[col0], lb1=s_lb[col0+1];
        mix[fi][0] += wv*((tv[fi][0]-mA)*rA2*lg0 + lb0);
        mix[fi][1] += wv*((tv[fi][1]-mA)*rA2*lg1 + lb1);
        mix[fi][2] += wv*((tv[fi][2]-mB)*rB2*lg0 + lb0);
        mix[fi][3] += wv*((tv[fi][3]-mB)*rB2*lg1 + lb1);
      }
    }
  }
  int rA = n0 + wr*16 + g;
  int rB = rA + 8;
  float* yout = g_gr + (size_t)(l+1)*NN*HH;
  #pragma unroll
  for (int f=0; f<4; f++){
    int col = wc*32 + f*8 + 2*tig;
    if (rA < NN) *(float2*)&yout[(size_t)rA*HH + col] = make_float2(mix[f][0], mix[f][1]);
    if (rB < NN) *(float2*)&yout[(size_t)rB*HH + col] = make_float2(mix[f][2], mix[f][3]);
  }
}

// ------------------------- BatchNorm stats (standalone, fused finisher) -------------------------
__global__ void k_bnstat(const float* __restrict__ bng, const float* __restrict__ bnb, int l){
  int t = threadIdx.x; int b = blockIdx.x;
  const float* y = g_gr + (size_t)(l+1)*NN*HH;
  float s=0.f, sq=0.f;
  for (int r=b; r<NN; r+=BNG){
    float v = y[(size_t)r*HH + t];
    s+=v; sq+=v*v;
  }
  g_part[b*HH+t]=s;
  g_part[BNG*HH + b*HH+t]=sq;
  __threadfence();
  __shared__ int lastS;
  if (t==0) lastS = (atomicAdd(&g_cbn,1) == BNG-1);
  __syncthreads();
  if (lastS){
    float ts=0.f, tq=0.f;
    for (int bb=0;bb<BNG;bb++){ ts+=g_part[bb*HH+t]; tq+=g_part[BNG*HH+bb*HH+t]; }
    float mean = ts*(1.f/NN);
    float var  = tq*(1.f/NN) - mean*mean;
    float sc = bng[l*HH+t]*rsqrtf(var+1e-5f);
    g_scA[(l+1)*HH+t] = sc;
    g_shA[(l+1)*HH+t] = bnb[l*HH+t]-mean*sc;
    if (t==0) g_cbn = 0;
  }
}

// ------------------------- virtual node MLP (vt fused into vnl1) -------------------------
__global__ void k_vnl1(const float* __restrict__ vn0,
                       const float* __restrict__ W1, const float* __restrict__ b1,
                       const float* __restrict__ bn_g, const float* __restrict__ bn_b, int l){
  __shared__ float vp[2][HH];
  __shared__ float vr[HH];
  __shared__ int lastS;
  int row=blockIdx.x, t=threadIdx.x;
  int s=g_bstart[row], e=g_bstart[row+1];
  {
    int half = t>>7, col = t&127;
    float acc=0.f;
    const float* gp = g_gr + (size_t)(l+1)*NN*HH;
    for (int r=s+half; r<e; r+=2) acc += gp[(size_t)r*HH+col];
    vp[half][col]=acc;
  }
  __syncthreads();
  if (t < HH){
    float sc = g_scA[(l+1)*HH+t], sh = g_shA[(l+1)*HH+t];
    float acc = (vp[0][t]+vp[1][t])*sc + (float)(e-s)*sh;
    float vnv;
    if (l == 0) vnv = vn0[t];
    else { float v = g_h2[row*HH+t]*g_sc2[t]+g_sh2[t]; vnv = v>0.f? v:0.f; }
    vr[t] = acc + vnv;
  }
  __syncthreads();
  float acc = b1[l*2*HH+t];
  const float* wp = W1 + (size_t)l*HH*2*HH + t;
  #pragma unroll 4
  for (int h=0;h<HH;h++) acc += vr[h]*wp[h*2*HH];
  g_h1[row*2*HH+t]=acc;
  __threadfence();
  if (t==0) lastS = (atomicAdd(&g_c1,1) == NB-1);
  __syncthreads();
  if (lastS){
    float s2=0.f, sq=0.f;
    for (int r=0;r<NB;r++){ float v=g_h1[r*2*HH+t]; s2+=v; sq+=v*v; }
    float mean=s2*(1.f/NB);
    float var=sq*(1.f/NB)-mean*mean;
    float sc = bn_g[l*2*HH+t]*rsqrtf(var+1e-5f);
    g_sc1[t]=sc;
    g_sh1[t]=bn_b[l*2*HH+t]-mean*sc;
    if (t==0) g_c1 = 0;
  }
}
__global__ void k_vnl2(const float* __restrict__ W2, const float* __restrict__ b2,
                       const float* __restrict__ bn_g, const float* __restrict__ bn_b, int l){
  __shared__ float hr[2*HH];
  __shared__ int lastS;
  int row=blockIdx.x, t=threadIdx.x;
  {
    float v0 = g_h1[row*2*HH+t]*g_sc1[t]+g_sh1[t];
    float v1 = g_h1[row*2*HH+t+HH]*g_sc1[t+HH]+g_sh1[t+HH];
    hr[t]    = v0>0.f? v0:0.f;
    hr[t+HH] = v1>0.f? v1:0.f;
  }
  __syncthreads();
  float acc = b2[l*HH+t];
  const float* wp = W2 + (size_t)l*2*HH*HH + t;
  #pragma unroll 4
  for (int h=0;h<2*HH;h++) acc += hr[h]*wp[h*HH];
  g_h2[row*HH+t]=acc;
  __threadfence();
  if (t==0) lastS = (atomicAdd(&g_c2,1) == NB-1);
  __syncthreads();
  if (lastS){
    float s=0.f, sq=0.f;
    for (int r=0;r<NB;r++){ float v=g_h2[r*HH+t]; s+=v; sq+=v*v; }
    float mean=s*(1.f/NB);
    float var=sq*(1.f/NB)-mean*mean;
    float sc = bn_g[l*HH+t]*rsqrtf(var+1e-5f);
    g_sc2[t]=sc;
    g_sh2[t]=bn_b[l*HH+t]-mean*sc;
    if (t==0) g_c2 = 0;
  }
}

// ------------------------- pooling + head (stage-parallel pool) -------------------------
__global__ void k_pool(){
  int b=blockIdx.x, st=blockIdx.y, t=threadIdx.x;
  int s=g_bstart[b], e=g_bstart[b+1];
  float inv = 1.f/(float)max(e-s,1);
  const float* gp = g_gr + (size_t)st*NN*HH;
  float sc = g_scA[st*HH+t], sh = g_shA[st*HH+t];
  float sum=0.f, mx=-1e30f;
  for (int r=s;r<e;r++){
    float v=gp[(size_t)r*HH+t]*sc+sh;
    sum+=v; mx=fmaxf(mx,v);
  }
  if (e==s) mx=0.f;
  g_pooled[b*1024 + st*HH + t] = sum*inv;
  g_pooled[b*1024 + 512 + st*HH + t] = mx;
}
__global__ void k_head(const float* __restrict__ hW, const float* __restrict__ hb,
                       const float* __restrict__ hM, float* __restrict__ out){
  __shared__ float red[NOUT];
  int b=blockIdx.x, t=threadIdx.x;
  if (t<NOUT) red[t]=0.f;
  __syncthreads();
  float acc[NOUT];
  #pragma unroll
  for (int j=0;j<NOUT;j++) acc[j]=0.f;
  for (int d=t; d<1024; d+=256){
    float pv = g_pooled[b*1024+d];
    const float* wrow = hW + d*NOUT;
    const float* mrow = hM + d*NOUT;
    #pragma unroll
    for (int j=0;j<NOUT;j++) acc[j] += pv*wrow[j]*mrow[j];
  }
  #pragma unroll
  for (int j=0;j<NOUT;j++) atomicAdd(&red[j], acc[j]);
  __syncthreads();
  if (t<NOUT) out[b*NOUT+t] = red[t] + hb[t];
}

// ------------------------- launch -------------------------
extern "C" void kernel_launch(void* const* d_in, const int* in_sizes, int n_in,
                              void* d_out, int out_size){
  const float* x      = (const float*)d_in[0];
  const int*   ei     = (const int*)d_in[1];
  const int*   batch  = (const int*)d_in[2];
  const float* lin1W  = (const float*)d_in[3];
  const float* lin1b  = (const float*)d_in[4];
  const float* vn0    = (const float*)d_in[5];
  const float* Wops   = (const float*)d_in[6];
  const float* bops   = (const float*)d_in[7];
  const float* atta   = (const float*)d_in[8];
  const float* lng    = (const float*)d_in[9];
  const float* lnb    = (const float*)d_in[10];
  const float* bng    = (const float*)d_in[11];
  const float* bnb    = (const float*)d_in[12];
  const float* vnW1   = (const float*)d_in[13];
  const float* vnb1   = (const float*)d_in[14];
  const float* vnbn1g = (const float*)d_in[15];
  const float* vnbn1b = (const float*)d_in[16];
  const float* vnW2   = (const float*)d_in[17];
  const float* vnb2   = (const float*)d_in[18];
  const float* vnbn2g = (const float*)d_in[19];
  const float* vnbn2b = (const float*)d_in[20];
  const float* alphas = (const float*)d_in[21];
  const float* headW  = (const float*)d_in[22];
  const float* headb  = (const float*)d_in[23];
  const float* headM  = (const float*)d_in[24];
  float* out = (float*)d_out;
  const int* src = ei;
  const int* dst = ei + NE;

  cudaFuncSetAttribute(k_mix_mma, cudaFuncAttributeMaxDynamicSharedMemorySize, SMEM_MIX);
  cudaFuncSetAttribute(k_lin1_mma, cudaFuncAttributeMaxDynamicSharedMemorySize, SMEM_L1);

  const int NBLK = (NN + 255)/256;
  const int WBLK = (NN*32 + 255)/256;
  const int EBLK = (NE + 255)/256;
  const int MIXBLK = (NN + MT-1)/MT;   // 782

  k_zero_deg<<<NBLK,256>>>();
  k_count<<<EBLK,256>>>(dst);
  k_scan<<<1,1024>>>();
  k_wprep1<<<(128*64+255)/256,256>>>(lin1W);
  k_wprep<<<(LL*NOPS*16384+255)/256,256>>>(Wops);
  k_lin1_mma<<<MIXBLK,256,SMEM_L1>>>(x, lin1b);
  k_scatter<<<EBLK,256>>>(src, dst);
  k_bstart<<<NBLK,256>>>(batch);
  k_prepw<<<1,128>>>(alphas);

  for (int l=0; l<LL; l++){
    k_nodeA<<<WBLK,256>>>(batch, atta, vn0, l);
    k_edge<<<WBLK,256>>>();
    k_mix_mma<<<MIXBLK,512,SMEM_MIX>>>(l, bops, lng, lnb);
    k_bnstat<<<BNG,128>>>(bng, bnb, l);
    if (l < LL-1){
      k_vnl1<<<NB,256>>>(vn0, vnW1, vnb1, vnbn1g, vnbn1b, l);
      k_vnl2<<<NB,128>>>(vnW2, vnb2, vnbn2g, vnbn2b, l);
    }
  }
  k_pool<<<dim3(NB,4),128>>>();
  k_head<<<NB,256>>>(headW, headb, headM, out);
}

// round 14
// speedup vs baseline: 1.0926x; 1.0926x over previous
#include <cuda_runtime.h>
#include <cuda_bf16.h>
#include <math.h>
#include <stdint.h>

#define NN 50000
#define NE 800000
#define FIN 64
#define HH 128
#define LL 3
#define CC 4
#define KK 32
#define NOPS 7
#define NB 512
#define NOUT 10
#define BNG 400

// ------------------------- device scratch (no allocs) -------------------------
__device__ float g_gr[(LL+1)*NN*HH];
__device__ float g_xw[NN*HH];
__device__ float g_sum[NN*HH];
__device__ float g_nrm[NN*HH];
__device__ float g_att[NN*HH];
__device__ float g_s0[NN];
__device__ float g_s1[NN];
__device__ float g_dinv[NN];
__device__ float g_minv[NN];
__device__ int   g_deg[NN];
__device__ int   g_rowptr[NN+1];
__device__ int   g_cursor[NN];
__device__ int   g_csrsrc[NE];
__device__ int   g_bstart[NB+1];
__device__ float g_wmix[LL*CC*NOPS];
__device__ float g_h1[NB*2*HH];
__device__ float g_h2[NB*HH];
__device__ float g_scA[(LL+1)*HH];
__device__ float g_shA[(LL+1)*HH];
__device__ float g_sc1[2*HH];
__device__ float g_sh1[2*HH];
__device__ float g_sc2[HH];
__device__ float g_sh2[HH];
__device__ float g_part[2*BNG*HH];
__device__ float g_pooled[NB*8*HH];
__device__ int   g_cbn = 0;
__device__ int   g_c1 = 0;
__device__ int   g_c2 = 0;
__device__ unsigned short g_Whi[LL*NOPS*16384];
__device__ unsigned short g_Wlo[LL*NOPS*16384];
__device__ unsigned short g_W1hi[128*64];
__device__ unsigned short g_W1lo[128*64];

// ------------------------- PTX helpers (baseline ISA, sm_80+) -------------------------
__device__ __forceinline__ uint32_t smem_u32(const void* p){
  uint32_t a; asm("{ .reg .u64 t; cvta.to.shared.u64 t, %1; cvt.u32.u64 %0, t; }" : "=r"(a) : "l"(p));
  return a;
}
__device__ __forceinline__ void ldsm4(uint32_t &r0, uint32_t &r1, uint32_t &r2, uint32_t &r3, uint32_t addr){
  asm volatile("ldmatrix.sync.aligned.m8n8.x4.shared.b16 {%0,%1,%2,%3}, [%4];"
    : "=r"(r0), "=r"(r1), "=r"(r2), "=r"(r3) : "r"(addr));
}
__device__ __forceinline__ void mma16816(float* d, const uint32_t* a, const uint32_t* b){
  asm volatile("mma.sync.aligned.m16n8k16.row.col.f32.bf16.bf16.f32 "
    "{%0,%1,%2,%3}, {%4,%5,%6,%7}, {%8,%9}, {%0,%1,%2,%3};"
    : "+f"(d[0]), "+f"(d[1]), "+f"(d[2]), "+f"(d[3])
    : "r"(a[0]), "r"(a[1]), "r"(a[2]), "r"(a[3]), "r"(b[0]), "r"(b[1]));
}
__device__ __forceinline__ void cpa16(uint32_t saddr, const void* gaddr){
  asm volatile("cp.async.cg.shared.global [%0], [%1], 16;" :: "r"(saddr), "l"(gaddr));
}
#define CPA_COMMIT() asm volatile("cp.async.commit_group;" ::: "memory")
#define CPA_WAIT()   asm volatile("cp.async.wait_group 0;" ::: "memory")

// ------------------------- CSR build -------------------------
__global__ void k_zero_deg(){
  int i = blockIdx.x*blockDim.x + threadIdx.x;
  if (i < NN) g_deg[i] = 0;
}
__global__ void k_count(const int* __restrict__ dst){
  int e = blockIdx.x*blockDim.x + threadIdx.x;
  if (e < NE) atomicAdd(&g_deg[dst[e]], 1);
}
__global__ void k_scan(){
  __shared__ int sm[1024];
  const int CH = (NN + 1023)/1024;
  int t = threadIdx.x;
  int s = 0;
  for (int i=0;i<CH;i++){ int idx = t*CH+i; if (idx<NN) s += g_deg[idx]; }
  sm[t] = s; __syncthreads();
  for (int off=1; off<1024; off<<=1){
    int v = (t>=off) ? sm[t-off] : 0;
    __syncthreads();
    if (t>=off) sm[t] += v;
    __syncthreads();
  }
  int run = (t>0)? sm[t-1] : 0;
  for (int i=0;i<CH;i++){
    int idx=t*CH+i;
    if (idx<NN){
      g_rowptr[idx]=run;
      g_cursor[idx]=run;
      int d = g_deg[idx];
      run += d;
      float dc = (float)max(d, 1);
      g_dinv[idx] = rsqrtf(dc);
      g_minv[idx] = 1.f/dc;
    }
  }
  if (t==1023) g_rowptr[NN] = sm[1023];
}
__global__ void k_scatter(const int* __restrict__ src, const int* __restrict__ dst){
  int e = blockIdx.x*blockDim.x + threadIdx.x;
  if (e < NE){
    int slot = atomicAdd(&g_cursor[dst[e]], 1);
    g_csrsrc[slot] = src[e];
  }
}
__global__ void k_bstart(const int* __restrict__ batch){
  int i = blockIdx.x*blockDim.x + threadIdx.x;
  if (i >= NN) return;
  int b = batch[i];
  if (i == 0){ for (int bb=0; bb<=b; bb++) g_bstart[bb] = 0; }
  else { int p = batch[i-1]; for (int bb=p+1; bb<=b; bb++) g_bstart[bb] = i; }
  if (i == NN-1){ for (int bb=b+1; bb<=NB; bb++) g_bstart[bb] = NN; }
}
__global__ void k_prepw(const float* __restrict__ alphas){
  int g = threadIdx.x;
  if (g < 128){ g_scA[g] = 1.f; g_shA[g] = 0.f; }
  if (g < LL*CC){
    const float* a = alphas + g*NOPS;
    float mx = a[0];
    for (int o=1;o<NOPS;o++) mx = fmaxf(mx, a[o]);
    float e[NOPS]; float s = 0.f;
    for (int o=0;o<NOPS;o++){ e[o] = expf(a[o]-mx); s += e[o]; }
    for (int o=0;o<NOPS;o++) g_wmix[g*NOPS+o] = e[o]/s;
  }
}

// ------------------------- weight prep -------------------------
__global__ void k_wprep(const float* __restrict__ Wops){
  int idx = blockIdx.x*blockDim.x + threadIdx.x;
  if (idx >= LL*NOPS*16384) return;
  int lop = idx >> 14;
  int el  = idx & 16383;
  int l = lop / NOPS, o = lop % NOPS;
  int r = el >> 7;
  int h = el & 127;
  int c = r >> 5, k = r & 31;
  float w = Wops[(((size_t)(l*CC + c)*NOPS + o)*HH + h)*KK + k];
  __nv_bfloat16 hb = __float2bfloat16(w);
  float res = w - __bfloat162float(hb);
  __nv_bfloat16 lb = __float2bfloat16(res);
  g_Whi[(size_t)lop*16384 + r*128 + h] = __bfloat16_as_ushort(hb);
  g_Wlo[(size_t)lop*16384 + r*128 + h] = __bfloat16_as_ushort(lb);
}
__global__ void k_wprep1(const float* __restrict__ W){
  int idx = blockIdx.x*blockDim.x + threadIdx.x;
  if (idx >= 128*64) return;
  int r = idx >> 6, h = idx & 63;
  float w = W[h*128 + r];
  __nv_bfloat16 hb = __float2bfloat16(w);
  float res = w - __bfloat162float(hb);
  __nv_bfloat16 lb = __float2bfloat16(res);
  g_W1hi[r*64+h] = __bfloat16_as_ushort(hb);
  g_W1lo[r*64+h] = __bfloat16_as_ushort(lb);
}

// ------------------------- lin1 + ELU via warp MMA -------------------------
#define PADK1 72
#define L1_AHI 0
#define L1_ALO (64*PADK1*2)
#define L1_WHI (2*64*PADK1*2)
#define L1_WLO (L1_WHI + 128*PADK1*2)
#define L1_BB  (L1_WLO + 128*PADK1*2)
#define SMEM_L1 (L1_BB + 512)

__global__ void __launch_bounds__(256,3) k_lin1_mma(const float* __restrict__ x,
    const float* __restrict__ bias){
  extern __shared__ char smc[];
  uint32_t sbase = smem_u32(smc);
  float* s_b1 = (float*)(smc + L1_BB);
  int tid = threadIdx.x;
  int lane = tid & 31, w = tid >> 5;
  int wr = w & 3, wc = w >> 2;
  int g = lane >> 2, tig = lane & 3;
  int n0 = blockIdx.x * 64;
  if (tid < 128) s_b1[tid] = bias[tid];

  #pragma unroll 1
  for (int it=0; it<8; it++){
    int wi = it*256 + tid;
    int r = wi >> 5;
    int h0 = (wi & 31)*2;
    int n = n0 + r;
    float vx=0.f, vy=0.f;
    if (n < NN){
      float2 a = *(const float2*)(x + (size_t)n*FIN + h0);
      vx=a.x; vy=a.y;
    }
    __nv_bfloat16 hx = __float2bfloat16(vx);
    __nv_bfloat16 hy = __float2bfloat16(vy);
    __nv_bfloat16 lx = __float2bfloat16(vx - __bfloat162float(hx));
    __nv_bfloat16 ly = __float2bfloat16(vy - __bfloat162float(hy));
    uint32_t off = (uint32_t)(r*PADK1 + h0)*2;
    *(uint32_t*)(smc + L1_AHI + off) = (uint32_t)__bfloat16_as_ushort(hx) | ((uint32_t)__bfloat16_as_ushort(hy)<<16);
    *(uint32_t*)(smc + L1_ALO + off) = (uint32_t)__bfloat16_as_ushort(lx) | ((uint32_t)__bfloat16_as_ushort(ly)<<16);
  }
  {
    const uint4* srcH = (const uint4*)g_W1hi;
    const uint4* srcL = (const uint4*)g_W1lo;
    #pragma unroll
    for (int it=0; it<4; it++){
      int i = it*256 + tid;
      int row = i >> 3, q = i & 7;
      uint32_t off = (uint32_t)(row*PADK1 + q*8)*2;
      *(uint4*)(smc + L1_WHI + off) = srcH[i];
      *(uint4*)(smc + L1_WLO + off) = srcL[i];
    }
  }
  __syncthreads();

  int a_off = ((lane&7) + ((lane>>3)&1)*8)*PADK1 + (lane>>4)*8;
  int b_off = (((lane>>4)&1)*8 + (lane&7))*PADK1 + ((lane>>3)&1)*8;
  uint32_t AbH = sbase + L1_AHI + (uint32_t)(wr*16*PADK1 + a_off)*2;
  uint32_t AbL = sbase + L1_ALO + (uint32_t)(wr*16*PADK1 + a_off)*2;
  uint32_t WbH = sbase + L1_WHI + (uint32_t)(wc*64*PADK1 + b_off)*2;
  uint32_t WbL = sbase + L1_WLO + (uint32_t)(wc*64*PADK1 + b_off)*2;

  float acc[8][4];
  #pragma unroll
  for (int f=0;f<8;f++){ acc[f][0]=0.f; acc[f][1]=0.f; acc[f][2]=0.f; acc[f][3]=0.f; }
  #pragma unroll
  for (int ks=0; ks<4; ks++){
    uint32_t k0b = (uint32_t)(ks*16)*2;
    uint32_t ah[4], al[4];
    ldsm4(ah[0],ah[1],ah[2],ah[3], AbH + k0b);
    ldsm4(al[0],al[1],al[2],al[3], AbL + k0b);
    #pragma unroll
    for (int nf=0; nf<4; nf++){
      uint32_t bh[4], bl[4];
      uint32_t woff = (uint32_t)(nf*16*PADK1)*2 + k0b;
      ldsm4(bh[0],bh[1],bh[2],bh[3], WbH + woff);
      ldsm4(bl[0],bl[1],bl[2],bl[3], WbL + woff);
      mma16816(acc[2*nf],   ah, bh);
      mma16816(acc[2*nf],   ah, bl);
      mma16816(acc[2*nf],   al, bh);
      mma16816(acc[2*nf+1], ah, bh+2);
      mma16816(acc[2*nf+1], ah, bl+2);
      mma16816(acc[2*nf+1], al, bh+2);
    }
  }
  int rA = n0 + wr*16 + g;
  int rB = rA + 8;
  #pragma unroll
  for (int f=0; f<8; f++){
    int col = wc*64 + f*8 + 2*tig;
    float b0 = s_b1[col], b1 = s_b1[col+1];
    float t0 = acc[f][0]+b0, t1 = acc[f][1]+b1;
    float t2 = acc[f][2]+b0, t3 = acc[f][3]+b1;
    t0 = t0>0.f ? t0 : expm1f(t0);
    t1 = t1>0.f ? t1 : expm1f(t1);
    t2 = t2>0.f ? t2 : expm1f(t2);
    t3 = t3>0.f ? t3 : expm1f(t3);
    if (rA < NN) *(float2*)&g_gr[(size_t)rA*HH + col] = make_float2(t0, t1);
    if (rB < NN) *(float2*)&g_gr[(size_t)rB*HH + col] = make_float2(t2, t3);
  }
}

// ------------------------- per-layer node prep (lazy BN affine + lazy vn) -------------------------
__global__ void k_nodeA(const int* __restrict__ batch, const float* __restrict__ atta,
                        const float* __restrict__ vn0, int l){
  int w = (blockIdx.x*blockDim.x + threadIdx.x) >> 5;
  int lane = threadIdx.x & 31;
  if (w >= NN) return;
  int b = batch[w];
  float4 xv = ((const float4*)(g_gr + (size_t)l*NN*HH))[w*32 + lane];
  float4 sc = ((const float4*)(g_scA + l*HH))[lane];
  float4 sh = ((const float4*)(g_shA + l*HH))[lane];
  xv.x = xv.x*sc.x+sh.x; xv.y = xv.y*sc.y+sh.y; xv.z = xv.z*sc.z+sh.z; xv.w = xv.w*sc.w+sh.w;
  float4 vv;
  if (l == 0){
    vv = ((const float4*)vn0)[lane];
  } else {
    float4 h2 = ((const float4*)g_h2)[b*32 + lane];
    float4 c2 = ((const float4*)g_sc2)[lane];
    float4 d2 = ((const float4*)g_sh2)[lane];
    vv.x = fmaxf(h2.x*c2.x+d2.x, 0.f);
    vv.y = fmaxf(h2.y*c2.y+d2.y, 0.f);
    vv.z = fmaxf(h2.z*c2.z+d2.z, 0.f);
    vv.w = fmaxf(h2.w*c2.w+d2.w, 0.f);
  }
  xv.x += vv.x; xv.y += vv.y; xv.z += vv.z; xv.w += vv.w;
  ((float4*)g_xw)[w*32 + lane] = xv;
  float4 a0 = ((const float4*)(atta + l*2*HH))[lane];
  float4 a1 = ((const float4*)(atta + l*2*HH + HH))[lane];
  float s0 = xv.x*a0.x + xv.y*a0.y + xv.z*a0.z + xv.w*a0.w;
  float s1 = xv.x*a1.x + xv.y*a1.y + xv.z*a1.z + xv.w*a1.w;
  #pragma unroll
  for (int off=16; off; off>>=1){
    s0 += __shfl_xor_sync(0xffffffffu, s0, off);
    s1 += __shfl_xor_sync(0xffffffffu, s1, off);
  }
  if (lane==0){ g_s0[w]=s0; g_s1[w]=s1; }
}

// ------------------------- fused attention + aggregation (warp per node) -------------------------
__global__ void k_edge(){
  int w = (blockIdx.x*blockDim.x + threadIdx.x) >> 5;
  int lane = threadIdx.x & 31;
  if (w >= NN) return;
  int s = g_rowptr[w], e = g_rowptr[w+1];
  float s1v = g_s1[w];
  float dv = g_dinv[w];
  float ss = 0.f;
  for (int j=s+lane; j<e; j+=32){
    float ev = g_s0[g_csrsrc[j]] + s1v;
    ev = ev>0.f ? ev : 0.2f*ev;
    ss += __expf(ev);
  }
  #pragma unroll
  for (int off=16; off; off>>=1) ss += __shfl_xor_sync(0xffffffffu, ss, off);
  float sinv = 1.f/(ss + 1e-16f);
  float4 a_s = make_float4(0.f,0.f,0.f,0.f);
  float4 a_n = a_s, a_a = a_s;
  int j = s;
  for (; j+4<=e; j+=4){
    int sn0=g_csrsrc[j], sn1=g_csrsrc[j+1], sn2=g_csrsrc[j+2], sn3=g_csrsrc[j+3];
    float4 x0 = ((const float4*)g_xw)[sn0*32 + lane];
    float4 x1 = ((const float4*)g_xw)[sn1*32 + lane];
    float4 x2 = ((const float4*)g_xw)[sn2*32 + lane];
    float4 x3 = ((const float4*)g_xw)[sn3*32 + lane];
    float e0=g_s0[sn0]+s1v, e1=g_s0[sn1]+s1v, e2=g_s0[sn2]+s1v, e3=g_s0[sn3]+s1v;
    e0 = e0>0.f? e0:0.2f*e0; e1 = e1>0.f? e1:0.2f*e1;
    e2 = e2>0.f? e2:0.2f*e2; e3 = e3>0.f? e3:0.2f*e3;
    float c0=__expf(e0)*sinv, c1=__expf(e1)*sinv, c2=__expf(e2)*sinv, c3=__expf(e3)*sinv;
    float w0=g_dinv[sn0]*dv, w1=g_dinv[sn1]*dv, w2=g_dinv[sn2]*dv, w3=g_dinv[sn3]*dv;
    a_s.x+=x0.x+x1.x+x2.x+x3.x; a_s.y+=x0.y+x1.y+x2.y+x3.y;
    a_s.z+=x0.z+x1.z+x2.z+x3.z; a_s.w+=x0.w+x1.w+x2.w+x3.w;
    a_n.x+=w0*x0.x+w1*x1.x+w2*x2.x+w3*x3.x; a_n.y+=w0*x0.y+w1*x1.y+w2*x2.y+w3*x3.y;
    a_n.z+=w0*x0.z+w1*x1.z+w2*x2.z+w3*x3.z; a_n.w+=w0*x0.w+w1*x1.w+w2*x2.w+w3*x3.w;
    a_a.x+=c0*x0.x+c1*x1.x+c2*x2.x+c3*x3.x; a_a.y+=c0*x0.y+c1*x1.y+c2*x2.y+c3*x3.y;
    a_a.z+=c0*x0.z+c1*x1.z+c2*x2.z+c3*x3.z; a_a.w+=c0*x0.w+c1*x1.w+c2*x2.w+c3*x3.w;
  }
  for (; j<e; j++){
    int sn = g_csrsrc[j];
    float ev = g_s0[sn] + s1v;
    ev = ev>0.f ? ev : 0.2f*ev;
    float ca = __expf(ev) * sinv;
    float nw = g_dinv[sn]*dv;
    float4 xv = ((const float4*)g_xw)[sn*32 + lane];
    a_s.x+=xv.x;      a_s.y+=xv.y;      a_s.z+=xv.z;      a_s.w+=xv.w;
    a_n.x+=nw*xv.x;   a_n.y+=nw*xv.y;   a_n.z+=nw*xv.z;   a_n.w+=nw*xv.w;
    a_a.x+=ca*xv.x;   a_a.y+=ca*xv.y;   a_a.z+=ca*xv.z;   a_a.w+=ca*xv.w;
  }
  ((float4*)g_sum)[w*32+lane]=a_s;
  ((float4*)g_nrm)[w*32+lane]=a_n;
  ((float4*)g_att)[w*32+lane]=a_a;
}

// ------------------------- warp-MMA mixed-op GEMM + LN + DARTS mix -------------------------
#define MT 64
#define PADK 136
#define SM_AHI 0
#define SM_ALO (MT*PADK*2)
#define SM_WHI (2*MT*PADK*2)
#define SM_WLO (SM_WHI + 128*PADK*2)
#define SM_BB  (SM_WLO + 128*PADK*2)
#define SM_LG  (SM_BB+512)
#define SM_LB  (SM_LG+512)
#define SMEM_MIX (SM_LB+512)

__constant__ int c_opseq[7] = {0,5,1,2,3,4,6};
__constant__ int c_asel[7]  = {0,0,1,2,3,4,5};

__global__ void __launch_bounds__(256,2) k_mix_mma(int l,
    const float* __restrict__ bops, const float* __restrict__ lng, const float* __restrict__ lnb){
  extern __shared__ char smc[];
  uint32_t sbase = smem_u32(smc);
  float* s_bb = (float*)(smc + SM_BB);
  float* s_lg = (float*)(smc + SM_LG);
  float* s_lb = (float*)(smc + SM_LB);
  int tid = threadIdx.x;
  int lane = tid & 31, w = tid >> 5;
  int wr = w & 3, wc = w >> 2;
  int g = lane >> 2, tig = lane & 3;
  int n0 = blockIdx.x * MT;
  if (tid < 128){ s_lg[tid] = lng[l*128+tid]; s_lb[tid] = lnb[l*128+tid]; }

  int a_off = ((lane&7) + ((lane>>3)&1)*8)*PADK + (lane>>4)*8;
  int b_off = (((lane>>4)&1)*8 + (lane&7))*PADK + ((lane>>3)&1)*8;
  uint32_t AbH = sbase + SM_AHI + (uint32_t)(wr*16*PADK + a_off)*2;
  uint32_t AbL = sbase + SM_ALO + (uint32_t)(wr*16*PADK + a_off)*2;
  uint32_t WbH = sbase + SM_WHI + (uint32_t)(wc*64*PADK)*2 + (uint32_t)b_off*2;
  uint32_t WbL = sbase + SM_WLO + (uint32_t)(wc*64*PADK)*2 + (uint32_t)b_off*2;

  float mix[8][4];
  #pragma unroll
  for (int f=0;f<8;f++){ mix[f][0]=0.f; mix[f][1]=0.f; mix[f][2]=0.f; mix[f][3]=0.f; }

  int prevA = -1;
  for (int oi=0; oi<7; oi++){
    int o = c_opseq[oi], asel = c_asel[oi];
    __syncthreads();
    // W tiles via cp.async — overlaps with A-build below
    {
      const uint4* srcH = (const uint4*)(g_Whi + (size_t)(l*NOPS+o)*16384);
      const uint4* srcL = (const uint4*)(g_Wlo + (size_t)(l*NOPS+o)*16384);
      #pragma unroll
      for (int it=0; it<8; it++){
        int i = it*256 + tid;
        int row = i >> 4, q = i & 15;
        uint32_t off = (uint32_t)(row*PADK + q*8)*2;
        cpa16(sbase + SM_WHI + off, srcH + i);
        cpa16(sbase + SM_WLO + off, srcL + i);
      }
      CPA_COMMIT();
    }
    if (asel != prevA){
      prevA = asel;
      #pragma unroll 1
      for (int it=0; it<16; it++){
        int wi = it*256 + tid;
        int r = wi >> 6;
        int h0 = (wi & 63)*2;
        int n = n0 + r;
        float vx=0.f, vy=0.f;
        if (n < NN){
          size_t base = (size_t)n*HH + h0;
          if (asel==0){ float2 a = *(const float2*)(g_nrm+base); vx=a.x; vy=a.y; }
          else if (asel==1){ float2 a=*(const float2*)(g_xw+base); float2 bq=*(const float2*)(g_sum+base); vx=a.x+bq.x; vy=a.y+bq.y; }
          else if (asel==2){ float2 a=*(const float2*)(g_att+base); vx=a.x; vy=a.y; }
          else if (asel==3){ float2 a=*(const float2*)(g_xw+base); float2 bq=*(const float2*)(g_sum+base); float m=g_minv[n]; vx=a.x+bq.x*m; vy=a.y+bq.y*m; }
          else if (asel==4){ float2 bq=*(const float2*)(g_sum+base); float m=g_minv[n]; vx=bq.x*m; vy=bq.y*m; }
          else { float2 a=*(const float2*)(g_xw+base); vx=a.x; vy=a.y; }
        }
        __nv_bfloat16 hx = __float2bfloat16(vx);
        __nv_bfloat16 hy = __float2bfloat16(vy);
        __nv_bfloat16 lx = __float2bfloat16(vx - __bfloat162float(hx));
        __nv_bfloat16 ly = __float2bfloat16(vy - __bfloat162float(hy));
        uint32_t off = (uint32_t)(r*PADK + h0)*2;
        *(uint32_t*)(smc + SM_AHI + off) = (uint32_t)__bfloat16_as_ushort(hx) | ((uint32_t)__bfloat16_as_ushort(hy)<<16);
        *(uint32_t*)(smc + SM_ALO + off) = (uint32_t)__bfloat16_as_ushort(lx) | ((uint32_t)__bfloat16_as_ushort(ly)<<16);
      }
    }
    if (tid < 128){
      int c = tid>>5, k = tid&31;
      s_bb[tid] = bops[((size_t)(l*CC + c)*NOPS + o)*KK + k];
    }
    CPA_WAIT();
    __syncthreads();

    float acc[8][4];
    #pragma unroll
    for (int f=0;f<8;f++){ acc[f][0]=0.f; acc[f][1]=0.f; acc[f][2]=0.f; acc[f][3]=0.f; }
    #pragma unroll 1
    for (int ks=0; ks<8; ks++){
      uint32_t k0b = (uint32_t)(ks*16)*2;
      uint32_t ah[4], al[4];
      ldsm4(ah[0],ah[1],ah[2],ah[3], AbH + k0b);
      ldsm4(al[0],al[1],al[2],al[3], AbL + k0b);
      #pragma unroll
      for (int nf=0; nf<4; nf++){
        uint32_t bh[4], bl[4];
        uint32_t woff = (uint32_t)(nf*16*PADK)*2 + k0b;
        ldsm4(bh[0],bh[1],bh[2],bh[3], WbH + woff);
        ldsm4(bl[0],bl[1],bl[2],bl[3], WbL + woff);
        mma16816(acc[2*nf],   ah, bh);
        mma16816(acc[2*nf],   ah, bl);
        mma16816(acc[2*nf],   al, bh);
        mma16816(acc[2*nf+1], ah, bh+2);
        mma16816(acc[2*nf+1], ah, bl+2);
        mma16816(acc[2*nf+1], al, bh+2);
      }
    }
    #pragma unroll
    for (int ch=0; ch<2; ch++){
      int c = wc*2 + ch;
      float tv[4][4];
      float sA=0.f, sqA=0.f, sB=0.f, sqB=0.f;
      #pragma unroll
      for (int fi=0; fi<4; fi++){
        int f = 4*ch + fi;
        int col0 = wc*64 + f*8 + 2*tig;
        float b0 = s_bb[col0], b1 = s_bb[col0+1];
        float t0 = acc[f][0]+b0, t1 = acc[f][1]+b1;
        float t2 = acc[f][2]+b0, t3 = acc[f][3]+b1;
        tv[fi][0]=t0; tv[fi][1]=t1; tv[fi][2]=t2; tv[fi][3]=t3;
        sA += t0+t1; sqA += t0*t0+t1*t1;
        sB += t2+t3; sqB += t2*t2+t3*t3;
      }
      sA += __shfl_xor_sync(0xffffffffu, sA, 1);  sqA += __shfl_xor_sync(0xffffffffu, sqA, 1);
      sB += __shfl_xor_sync(0xffffffffu, sB, 1);  sqB += __shfl_xor_sync(0xffffffffu, sqB, 1);
      sA += __shfl_xor_sync(0xffffffffu, sA, 2);  sqA += __shfl_xor_sync(0xffffffffu, sqA, 2);
      sB += __shfl_xor_sync(0xffffffffu, sB, 2);  sqB += __shfl_xor_sync(0xffffffffu, sqB, 2);
      float mA = sA*(1.f/32.f), vA = sqA*(1.f/32.f) - mA*mA;
      float mB = sB*(1.f/32.f), vB = sqB*(1.f/32.f) - mB*mB;
      float rA2 = rsqrtf(vA + 1e-5f), rB2 = rsqrtf(vB + 1e-5f);
      float wv = g_wmix[(l*CC + c)*NOPS + o];
      #pragma unroll
      for (int fi=0; fi<4; fi++){
        int f = 4*ch + fi;
        int col0 = wc*64 + f*8 + 2*tig;
        float lg0=s_lg[col0], lg1=s_lg[col0+1], lb0=s_lb[col0], lb1=s_lb[col0+1];
        mix[f][0] += wv*((tv[fi][0]-mA)*rA2*lg0 + lb0);
        mix[f][1] += wv*((tv[fi][1]-mA)*rA2*lg1 + lb1);
        mix[f][2] += wv*((tv[fi][2]-mB)*rB2*lg0 + lb0);
        mix[f][3] += wv*((tv[fi][3]-mB)*rB2*lg1 + lb1);
      }
    }
  }
  int rA = n0 + wr*16 + g;
  int rB = rA + 8;
  float* yout = g_gr + (size_t)(l+1)*NN*HH;
  #pragma unroll
  for (int f=0; f<8; f++){
    int col = wc*64 + f*8 + 2*tig;
    if (rA < NN) *(float2*)&yout[(size_t)rA*HH + col] = make_float2(mix[f][0], mix[f][1]);
    if (rB < NN) *(float2*)&yout[(size_t)rB*HH + col] = make_float2(mix[f][2], mix[f][3]);
  }
}

// ------------------------- BatchNorm stats (standalone, fused finisher) -------------------------
__global__ void k_bnstat(const float* __restrict__ bng, const float* __restrict__ bnb, int l){
  int t = threadIdx.x; int b = blockIdx.x;
  const float* y = g_gr + (size_t)(l+1)*NN*HH;
  float s=0.f, sq=0.f;
  for (int r=b; r<NN; r+=BNG){
    float v = y[(size_t)r*HH + t];
    s+=v; sq+=v*v;
  }
  g_part[b*HH+t]=s;
  g_part[BNG*HH + b*HH+t]=sq;
  __threadfence();
  __shared__ int lastS;
  if (t==0) lastS = (atomicAdd(&g_cbn,1) == BNG-1);
  __syncthreads();
  if (lastS){
    float ts=0.f, tq=0.f;
    for (int bb=0;bb<BNG;bb++){ ts+=g_part[bb*HH+t]; tq+=g_part[BNG*HH+bb*HH+t]; }
    float mean = ts*(1.f/NN);
    float var  = tq*(1.f/NN) - mean*mean;
    float sc = bng[l*HH+t]*rsqrtf(var+1e-5f);
    g_scA[(l+1)*HH+t] = sc;
    g_shA[(l+1)*HH+t] = bnb[l*HH+t]-mean*sc;
    if (t==0) g_cbn = 0;
  }
}

// ------------------------- virtual node MLP (vt fused into vnl1) -------------------------
__global__ void k_vnl1(const float* __restrict__ vn0,
                       const float* __restrict__ W1, const float* __restrict__ b1,
                       const float* __restrict__ bn_g, const float* __restrict__ bn_b, int l){
  __shared__ float vp[2][HH];
  __shared__ float vr[HH];
  __shared__ int lastS;
  int row=blockIdx.x, t=threadIdx.x;
  int s=g_bstart[row], e=g_bstart[row+1];
  {
    int half = t>>7, col = t&127;
    float acc=0.f;
    const float* gp = g_gr + (size_t)(l+1)*NN*HH;
    for (int r=s+half; r<e; r+=2) acc += gp[(size_t)r*HH+col];
    vp[half][col]=acc;
  }
  __syncthreads();
  if (t < HH){
    float sc = g_scA[(l+1)*HH+t], sh = g_shA[(l+1)*HH+t];
    float acc = (vp[0][t]+vp[1][t])*sc + (float)(e-s)*sh;
    float vnv;
    if (l == 0) vnv = vn0[t];
    else { float v = g_h2[row*HH+t]*g_sc2[t]+g_sh2[t]; vnv = v>0.f? v:0.f; }
    vr[t] = acc + vnv;
  }
  __syncthreads();
  float acc = b1[l*2*HH+t];
  const float* wp = W1 + (size_t)l*HH*2*HH + t;
  #pragma unroll 4
  for (int h=0;h<HH;h++) acc += vr[h]*wp[h*2*HH];
  g_h1[row*2*HH+t]=acc;
  __threadfence();
  if (t==0) lastS = (atomicAdd(&g_c1,1) == NB-1);
  __syncthreads();
  if (lastS){
    float s2=0.f, sq=0.f;
    for (int r=0;r<NB;r++){ float v=g_h1[r*2*HH+t]; s2+=v; sq+=v*v; }
    float mean=s2*(1.f/NB);
    float var=sq*(1.f/NB)-mean*mean;
    float sc = bn_g[l*2*HH+t]*rsqrtf(var+1e-5f);
    g_sc1[t]=sc;
    g_sh1[t]=bn_b[l*2*HH+t]-mean*sc;
    if (t==0) g_c1 = 0;
  }
}
__global__ void k_vnl2(const float* __restrict__ W2, const float* __restrict__ b2,
                       const float* __restrict__ bn_g, const float* __restrict__ bn_b, int l){
  __shared__ float hr[2*HH];
  __shared__ int lastS;
  int row=blockIdx.x, t=threadIdx.x;
  {
    float v0 = g_h1[row*2*HH+t]*g_sc1[t]+g_sh1[t];
    float v1 = g_h1[row*2*HH+t+HH]*g_sc1[t+HH]+g_sh1[t+HH];
    hr[t]    = v0>0.f? v0:0.f;
    hr[t+HH] = v1>0.f? v1:0.f;
  }
  __syncthreads();
  float acc = b2[l*HH+t];
  const float* wp = W2 + (size_t)l*2*HH*HH + t;
  #pragma unroll 4
  for (int h=0;h<2*HH;h++) acc += hr[h]*wp[h*HH];
  g_h2[row*HH+t]=acc;
  __threadfence();
  if (t==0) lastS = (atomicAdd(&g_c2,1) == NB-1);
  __syncthreads();
  if (lastS){
    float s=0.f, sq=0.f;
    for (int r=0;r<NB;r++){ float v=g_h2[r*HH+t]; s+=v; sq+=v*v; }
    float mean=s*(1.f/NB);
    float var=sq*(1.f/NB)-mean*mean;
    float sc = bn_g[l*HH+t]*rsqrtf(var+1e-5f);
    g_sc2[t]=sc;
    g_sh2[t]=bn_b[l*HH+t]-mean*sc;
    if (t==0) g_c2 = 0;
  }
}

// ------------------------- pooling + head (stage-parallel pool) -------------------------
__global__ void k_pool(){
  int b=blockIdx.x, st=blockIdx.y, t=threadIdx.x;
  int s=g_bstart[b], e=g_bstart[b+1];
  float inv = 1.f/(float)max(e-s,1);
  const float* gp = g_gr + (size_t)st*NN*HH;
  float sc = g_scA[st*HH+t], sh = g_shA[st*HH+t];
  float sum=0.f, mx=-1e30f;
  for (int r=s;r<e;r++){
    float v=gp[(size_t)r*HH+t]*sc+sh;
    sum+=v; mx=fmaxf(mx,v);
  }
  if (e==s) mx=0.f;
  g_pooled[b*1024 + st*HH + t] = sum*inv;
  g_pooled[b*1024 + 512 + st*HH + t] = mx;
}
__global__ void k_head(const float* __restrict__ hW, const float* __restrict__ hb,
                       const float* __restrict__ hM, float* __restrict__ out){
  __shared__ float red[NOUT];
  int b=blockIdx.x, t=threadIdx.x;
  if (t<NOUT) red[t]=0.f;
  __syncthreads();
  float acc[NOUT];
  #pragma unroll
  for (int j=0;j<NOUT;j++) acc[j]=0.f;
  for (int d=t; d<1024; d+=256){
    float pv = g_pooled[b*1024+d];
    const float* wrow = hW + d*NOUT;
    const float* mrow = hM + d*NOUT;
    #pragma unroll
    for (int j=0;j<NOUT;j++) acc[j] += pv*wrow[j]*mrow[j];
  }
  #pragma unroll
  for (int j=0;j<NOUT;j++) atomicAdd(&red[j], acc[j]);
  __syncthreads();
  if (t<NOUT) out[b*NOUT+t] = red[t] + hb[t];
}

// ------------------------- launch -------------------------
extern "C" void kernel_launch(void* const* d_in, const int* in_sizes, int n_in,
                              void* d_out, int out_size){
  const float* x      = (const float*)d_in[0];
  const int*   ei     = (const int*)d_in[1];
  const int*   batch  = (const int*)d_in[2];
  const float* lin1W  = (const float*)d_in[3];
  const float* lin1b  = (const float*)d_in[4];
  const float* vn0    = (const float*)d_in[5];
  const float* Wops   = (const float*)d_in[6];
  const float* bops   = (const float*)d_in[7];
  const float* atta   = (const float*)d_in[8];
  const float* lng    = (const float*)d_in[9];
  const float* lnb    = (const float*)d_in[10];
  const float* bng    = (const float*)d_in[11];
  const float* bnb    = (const float*)d_in[12];
  const float* vnW1   = (const float*)d_in[13];
  const float* vnb1   = (const float*)d_in[14];
  const float* vnbn1g = (const float*)d_in[15];
  const float* vnbn1b = (const float*)d_in[16];
  const float* vnW2   = (const float*)d_in[17];
  const float* vnb2   = (const float*)d_in[18];
  const float* vnbn2g = (const float*)d_in[19];
  const float* vnbn2b = (const float*)d_in[20];
  const float* alphas = (const float*)d_in[21];
  const float* headW  = (const float*)d_in[22];
  const float* headb  = (const float*)d_in[23];
  const float* headM  = (const float*)d_in[24];
  float* out = (float*)d_out;
  const int* src = ei;
  const int* dst = ei + NE;

  cudaFuncSetAttribute(k_mix_mma, cudaFuncAttributeMaxDynamicSharedMemorySize, SMEM_MIX);
  cudaFuncSetAttribute(k_lin1_mma, cudaFuncAttributeMaxDynamicSharedMemorySize, SMEM_L1);

  const int NBLK = (NN + 255)/256;
  const int WBLK = (NN*32 + 255)/256;
  const int EBLK = (NE + 255)/256;
  const int MIXBLK = (NN + MT-1)/MT;   // 782

  k_zero_deg<<<NBLK,256>>>();
  k_count<<<EBLK,256>>>(dst);
  k_scan<<<1,1024>>>();
  k_wprep1<<<(128*64+255)/256,256>>>(lin1W);
  k_wprep<<<(LL*NOPS*16384+255)/256,256>>>(Wops);
  k_lin1_mma<<<MIXBLK,256,SMEM_L1>>>(x, lin1b);
  k_scatter<<<EBLK,256>>>(src, dst);
  k_bstart<<<NBLK,256>>>(batch);
  k_prepw<<<1,128>>>(alphas);

  for (int l=0; l<LL; l++){
    k_nodeA<<<WBLK,256>>>(batch, atta, vn0, l);
    k_edge<<<WBLK,256>>>();
    k_mix_mma<<<MIXBLK,256,SMEM_MIX>>>(l, bops, lng, lnb);
    k_bnstat<<<BNG,128>>>(bng, bnb, l);
    if (l < LL-1){
      k_vnl1<<<NB,256>>>(vn0, vnW1, vnb1, vnbn1g, vnbn1b, l);
      k_vnl2<<<NB,128>>>(vnW2, vnb2, vnbn2g, vnbn2b, l);
    }
  }
  k_pool<<<dim3(NB,4),128>>>();
  k_head<<<NB,256>>>(headW, headb, headM, out);
}

// round 15
// speedup vs baseline: 1.1026x; 1.0092x over previous
#include <cuda_runtime.h>
#include <cuda_bf16.h>
#include <math.h>
#include <stdint.h>

#define NN 50000
#define NE 800000
#define FIN 64
#define HH 128
#define LL 3
#define CC 4
#define KK 32
#define NOPS 7
#define NB 512
#define NOUT 10
#define BNG 400

// ------------------------- device scratch (no allocs) -------------------------
__device__ float g_gr[(LL+1)*NN*HH];
__device__ float g_xw[NN*HH];
__device__ float g_sum[NN*HH];
__device__ float g_nrm[NN*HH];
__device__ float g_att[NN*HH];
__device__ float g_s0[NN];
__device__ float g_s1[NN];
__device__ float g_dinv[NN];
__device__ float g_minv[NN];
__device__ int   g_deg[NN];
__device__ int   g_rowptr[NN+1];
__device__ int   g_cursor[NN];
__device__ int   g_csrsrc[NE];
__device__ int   g_bstart[NB+1];
__device__ float g_wmix[LL*CC*NOPS];
__device__ float g_h1[NB*2*HH];
__device__ float g_h2[NB*HH];
__device__ float g_scA[(LL+1)*HH];
__device__ float g_shA[(LL+1)*HH];
__device__ float g_sc1[2*HH];
__device__ float g_sh1[2*HH];
__device__ float g_sc2[HH];
__device__ float g_sh2[HH];
__device__ float g_part[2*BNG*HH];
__device__ float g_pooled[NB*8*HH];
__device__ int   g_cbn = 0;
__device__ int   g_c1 = 0;
__device__ int   g_c2 = 0;
__device__ unsigned short g_Whi[LL*NOPS*16384];
__device__ unsigned short g_Wlo[LL*NOPS*16384];
__device__ unsigned short g_W1hi[128*64];
__device__ unsigned short g_W1lo[128*64];

// ------------------------- PTX helpers (baseline ISA, sm_80+) -------------------------
__device__ __forceinline__ uint32_t smem_u32(const void* p){
  uint32_t a; asm("{ .reg .u64 t; cvta.to.shared.u64 t, %1; cvt.u32.u64 %0, t; }" : "=r"(a) : "l"(p));
  return a;
}
__device__ __forceinline__ void ldsm4(uint32_t &r0, uint32_t &r1, uint32_t &r2, uint32_t &r3, uint32_t addr){
  asm volatile("ldmatrix.sync.aligned.m8n8.x4.shared.b16 {%0,%1,%2,%3}, [%4];"
    : "=r"(r0), "=r"(r1), "=r"(r2), "=r"(r3) : "r"(addr));
}
__device__ __forceinline__ void mma16816(float* d, const uint32_t* a, const uint32_t* b){
  asm volatile("mma.sync.aligned.m16n8k16.row.col.f32.bf16.bf16.f32 "
    "{%0,%1,%2,%3}, {%4,%5,%6,%7}, {%8,%9}, {%0,%1,%2,%3};"
    : "+f"(d[0]), "+f"(d[1]), "+f"(d[2]), "+f"(d[3])
    : "r"(a[0]), "r"(a[1]), "r"(a[2]), "r"(a[3]), "r"(b[0]), "r"(b[1]));
}
__device__ __forceinline__ void cpa16(uint32_t saddr, const void* gaddr){
  asm volatile("cp.async.cg.shared.global [%0], [%1], 16;" :: "r"(saddr), "l"(gaddr));
}
#define CPA_COMMIT() asm volatile("cp.async.commit_group;" ::: "memory")
#define CPA_WAIT()   asm volatile("cp.async.wait_group 0;" ::: "memory")

// ------------------------- CSR build -------------------------
__global__ void k_zero_deg(){
  int i = blockIdx.x*blockDim.x + threadIdx.x;
  if (i < NN) g_deg[i] = 0;
}
__global__ void k_count(const int* __restrict__ dst){
  int e = blockIdx.x*blockDim.x + threadIdx.x;
  if (e < NE) atomicAdd(&g_deg[dst[e]], 1);
}
__global__ void k_scan(){
  __shared__ int sm[1024];
  const int CH = (NN + 1023)/1024;
  int t = threadIdx.x;
  int s = 0;
  for (int i=0;i<CH;i++){ int idx = t*CH+i; if (idx<NN) s += g_deg[idx]; }
  sm[t] = s; __syncthreads();
  for (int off=1; off<1024; off<<=1){
    int v = (t>=off) ? sm[t-off] : 0;
    __syncthreads();
    if (t>=off) sm[t] += v;
    __syncthreads();
  }
  int run = (t>0)? sm[t-1] : 0;
  for (int i=0;i<CH;i++){
    int idx=t*CH+i;
    if (idx<NN){
      g_rowptr[idx]=run;
      g_cursor[idx]=run;
      int d = g_deg[idx];
      run += d;
      float dc = (float)max(d, 1);
      g_dinv[idx] = rsqrtf(dc);
      g_minv[idx] = 1.f/dc;
    }
  }
  if (t==1023) g_rowptr[NN] = sm[1023];
}
__global__ void k_scatter(const int* __restrict__ src, const int* __restrict__ dst){
  int e = blockIdx.x*blockDim.x + threadIdx.x;
  if (e < NE){
    int slot = atomicAdd(&g_cursor[dst[e]], 1);
    g_csrsrc[slot] = src[e];
  }
}
__global__ void k_bstart(const int* __restrict__ batch){
  int i = blockIdx.x*blockDim.x + threadIdx.x;
  if (i >= NN) return;
  int b = batch[i];
  if (i == 0){ for (int bb=0; bb<=b; bb++) g_bstart[bb] = 0; }
  else { int p = batch[i-1]; for (int bb=p+1; bb<=b; bb++) g_bstart[bb] = i; }
  if (i == NN-1){ for (int bb=b+1; bb<=NB; bb++) g_bstart[bb] = NN; }
}
__global__ void k_prepw(const float* __restrict__ alphas){
  int g = threadIdx.x;
  if (g < 128){ g_scA[g] = 1.f; g_shA[g] = 0.f; }
  if (g < LL*CC){
    const float* a = alphas + g*NOPS;
    float mx = a[0];
    for (int o=1;o<NOPS;o++) mx = fmaxf(mx, a[o]);
    float e[NOPS]; float s = 0.f;
    for (int o=0;o<NOPS;o++){ e[o] = expf(a[o]-mx); s += e[o]; }
    for (int o=0;o<NOPS;o++) g_wmix[g*NOPS+o] = e[o]/s;
  }
}

// ------------------------- weight prep -------------------------
__global__ void k_wprep(const float* __restrict__ Wops){
  int idx = blockIdx.x*blockDim.x + threadIdx.x;
  if (idx >= LL*NOPS*16384) return;
  int lop = idx >> 14;
  int el  = idx & 16383;
  int l = lop / NOPS, o = lop % NOPS;
  int r = el >> 7;
  int h = el & 127;
  int c = r >> 5, k = r & 31;
  float w = Wops[(((size_t)(l*CC + c)*NOPS + o)*HH + h)*KK + k];
  __nv_bfloat16 hb = __float2bfloat16(w);
  float res = w - __bfloat162float(hb);
  __nv_bfloat16 lb = __float2bfloat16(res);
  g_Whi[(size_t)lop*16384 + r*128 + h] = __bfloat16_as_ushort(hb);
  g_Wlo[(size_t)lop*16384 + r*128 + h] = __bfloat16_as_ushort(lb);
}
__global__ void k_wprep1(const float* __restrict__ W){
  int idx = blockIdx.x*blockDim.x + threadIdx.x;
  if (idx >= 128*64) return;
  int r = idx >> 6, h = idx & 63;
  float w = W[h*128 + r];
  __nv_bfloat16 hb = __float2bfloat16(w);
  float res = w - __bfloat162float(hb);
  __nv_bfloat16 lb = __float2bfloat16(res);
  g_W1hi[r*64+h] = __bfloat16_as_ushort(hb);
  g_W1lo[r*64+h] = __bfloat16_as_ushort(lb);
}

// ------------------------- lin1 + ELU via warp MMA -------------------------
#define PADK1 72
#define L1_AHI 0
#define L1_ALO (64*PADK1*2)
#define L1_WHI (2*64*PADK1*2)
#define L1_WLO (L1_WHI + 128*PADK1*2)
#define L1_BB  (L1_WLO + 128*PADK1*2)
#define SMEM_L1 (L1_BB + 512)

__global__ void __launch_bounds__(256,3) k_lin1_mma(const float* __restrict__ x,
    const float* __restrict__ bias){
  extern __shared__ char smc[];
  uint32_t sbase = smem_u32(smc);
  float* s_b1 = (float*)(smc + L1_BB);
  int tid = threadIdx.x;
  int lane = tid & 31, w = tid >> 5;
  int wr = w & 3, wc = w >> 2;
  int g = lane >> 2, tig = lane & 3;
  int n0 = blockIdx.x * 64;
  if (tid < 128) s_b1[tid] = bias[tid];

  #pragma unroll 1
  for (int it=0; it<8; it++){
    int wi = it*256 + tid;
    int r = wi >> 5;
    int h0 = (wi & 31)*2;
    int n = n0 + r;
    float vx=0.f, vy=0.f;
    if (n < NN){
      float2 a = *(const float2*)(x + (size_t)n*FIN + h0);
      vx=a.x; vy=a.y;
    }
    __nv_bfloat16 hx = __float2bfloat16(vx);
    __nv_bfloat16 hy = __float2bfloat16(vy);
    __nv_bfloat16 lx = __float2bfloat16(vx - __bfloat162float(hx));
    __nv_bfloat16 ly = __float2bfloat16(vy - __bfloat162float(hy));
    uint32_t off = (uint32_t)(r*PADK1 + h0)*2;
    *(uint32_t*)(smc + L1_AHI + off) = (uint32_t)__bfloat16_as_ushort(hx) | ((uint32_t)__bfloat16_as_ushort(hy)<<16);
    *(uint32_t*)(smc + L1_ALO + off) = (uint32_t)__bfloat16_as_ushort(lx) | ((uint32_t)__bfloat16_as_ushort(ly)<<16);
  }
  {
    const uint4* srcH = (const uint4*)g_W1hi;
    const uint4* srcL = (const uint4*)g_W1lo;
    #pragma unroll
    for (int it=0; it<4; it++){
      int i = it*256 + tid;
      int row = i >> 3, q = i & 7;
      uint32_t off = (uint32_t)(row*PADK1 + q*8)*2;
      *(uint4*)(smc + L1_WHI + off) = srcH[i];
      *(uint4*)(smc + L1_WLO + off) = srcL[i];
    }
  }
  __syncthreads();

  int a_off = ((lane&7) + ((lane>>3)&1)*8)*PADK1 + (lane>>4)*8;
  int b_off = (((lane>>4)&1)*8 + (lane&7))*PADK1 + ((lane>>3)&1)*8;
  uint32_t AbH = sbase + L1_AHI + (uint32_t)(wr*16*PADK1 + a_off)*2;
  uint32_t AbL = sbase + L1_ALO + (uint32_t)(wr*16*PADK1 + a_off)*2;
  uint32_t WbH = sbase + L1_WHI + (uint32_t)(wc*64*PADK1 + b_off)*2;
  uint32_t WbL = sbase + L1_WLO + (uint32_t)(wc*64*PADK1 + b_off)*2;

  float acc[8][4];
  #pragma unroll
  for (int f=0;f<8;f++){ acc[f][0]=0.f; acc[f][1]=0.f; acc[f][2]=0.f; acc[f][3]=0.f; }
  #pragma unroll
  for (int ks=0; ks<4; ks++){
    uint32_t k0b = (uint32_t)(ks*16)*2;
    uint32_t ah[4], al[4];
    ldsm4(ah[0],ah[1],ah[2],ah[3], AbH + k0b);
    ldsm4(al[0],al[1],al[2],al[3], AbL + k0b);
    #pragma unroll
    for (int nf=0; nf<4; nf++){
      uint32_t bh[4], bl[4];
      uint32_t woff = (uint32_t)(nf*16*PADK1)*2 + k0b;
      ldsm4(bh[0],bh[1],bh[2],bh[3], WbH + woff);
      ldsm4(bl[0],bl[1],bl[2],bl[3], WbL + woff);
      mma16816(acc[2*nf],   ah, bh);
      mma16816(acc[2*nf],   ah, bl);
      mma16816(acc[2*nf],   al, bh);
      mma16816(acc[2*nf+1], ah, bh+2);
      mma16816(acc[2*nf+1], ah, bl+2);
      mma16816(acc[2*nf+1], al, bh+2);
    }
  }
  int rA = n0 + wr*16 + g;
  int rB = rA + 8;
  #pragma unroll
  for (int f=0; f<8; f++){
    int col = wc*64 + f*8 + 2*tig;
    float b0 = s_b1[col], b1 = s_b1[col+1];
    float t0 = acc[f][0]+b0, t1 = acc[f][1]+b1;
    float t2 = acc[f][2]+b0, t3 = acc[f][3]+b1;
    t0 = t0>0.f ? t0 : expm1f(t0);
    t1 = t1>0.f ? t1 : expm1f(t1);
    t2 = t2>0.f ? t2 : expm1f(t2);
    t3 = t3>0.f ? t3 : expm1f(t3);
    if (rA < NN) *(float2*)&g_gr[(size_t)rA*HH + col] = make_float2(t0, t1);
    if (rB < NN) *(float2*)&g_gr[(size_t)rB*HH + col] = make_float2(t2, t3);
  }
}

// ------------------------- per-layer node prep (lazy BN affine + lazy vn) -------------------------
__global__ void k_nodeA(const int* __restrict__ batch, const float* __restrict__ atta,
                        const float* __restrict__ vn0, int l){
  int w = (blockIdx.x*blockDim.x + threadIdx.x) >> 5;
  int lane = threadIdx.x & 31;
  if (w >= NN) return;
  int b = batch[w];
  float4 xv = ((const float4*)(g_gr + (size_t)l*NN*HH))[w*32 + lane];
  float4 sc = ((const float4*)(g_scA + l*HH))[lane];
  float4 sh = ((const float4*)(g_shA + l*HH))[lane];
  xv.x = xv.x*sc.x+sh.x; xv.y = xv.y*sc.y+sh.y; xv.z = xv.z*sc.z+sh.z; xv.w = xv.w*sc.w+sh.w;
  float4 vv;
  if (l == 0){
    vv = ((const float4*)vn0)[lane];
  } else {
    float4 h2 = ((const float4*)g_h2)[b*32 + lane];
    float4 c2 = ((const float4*)g_sc2)[lane];
    float4 d2 = ((const float4*)g_sh2)[lane];
    vv.x = fmaxf(h2.x*c2.x+d2.x, 0.f);
    vv.y = fmaxf(h2.y*c2.y+d2.y, 0.f);
    vv.z = fmaxf(h2.z*c2.z+d2.z, 0.f);
    vv.w = fmaxf(h2.w*c2.w+d2.w, 0.f);
  }
  xv.x += vv.x; xv.y += vv.y; xv.z += vv.z; xv.w += vv.w;
  ((float4*)g_xw)[w*32 + lane] = xv;
  float4 a0 = ((const float4*)(atta + l*2*HH))[lane];
  float4 a1 = ((const float4*)(atta + l*2*HH + HH))[lane];
  float s0 = xv.x*a0.x + xv.y*a0.y + xv.z*a0.z + xv.w*a0.w;
  float s1 = xv.x*a1.x + xv.y*a1.y + xv.z*a1.z + xv.w*a1.w;
  #pragma unroll
  for (int off=16; off; off>>=1){
    s0 += __shfl_xor_sync(0xffffffffu, s0, off);
    s1 += __shfl_xor_sync(0xffffffffu, s1, off);
  }
  if (lane==0){ g_s0[w]=s0; g_s1[w]=s1; }
}

// ------------------------- fused attention + aggregation (warp per node) -------------------------
__global__ void k_edge(){
  int w = (blockIdx.x*blockDim.x + threadIdx.x) >> 5;
  int lane = threadIdx.x & 31;
  if (w >= NN) return;
  int s = g_rowptr[w], e = g_rowptr[w+1];
  float s1v = g_s1[w];
  float dv = g_dinv[w];
  float ss = 0.f;
  for (int j=s+lane; j<e; j+=32){
    float ev = g_s0[g_csrsrc[j]] + s1v;
    ev = ev>0.f ? ev : 0.2f*ev;
    ss += __expf(ev);
  }
  #pragma unroll
  for (int off=16; off; off>>=1) ss += __shfl_xor_sync(0xffffffffu, ss, off);
  float sinv = 1.f/(ss + 1e-16f);
  float4 a_s = make_float4(0.f,0.f,0.f,0.f);
  float4 a_n = a_s, a_a = a_s;
  int j = s;
  for (; j+4<=e; j+=4){
    int sn0=g_csrsrc[j], sn1=g_csrsrc[j+1], sn2=g_csrsrc[j+2], sn3=g_csrsrc[j+3];
    float4 x0 = ((const float4*)g_xw)[sn0*32 + lane];
    float4 x1 = ((const float4*)g_xw)[sn1*32 + lane];
    float4 x2 = ((const float4*)g_xw)[sn2*32 + lane];
    float4 x3 = ((const float4*)g_xw)[sn3*32 + lane];
    float e0=g_s0[sn0]+s1v, e1=g_s0[sn1]+s1v, e2=g_s0[sn2]+s1v, e3=g_s0[sn3]+s1v;
    e0 = e0>0.f? e0:0.2f*e0; e1 = e1>0.f? e1:0.2f*e1;
    e2 = e2>0.f? e2:0.2f*e2; e3 = e3>0.f? e3:0.2f*e3;
    float c0=__expf(e0)*sinv, c1=__expf(e1)*sinv, c2=__expf(e2)*sinv, c3=__expf(e3)*sinv;
    float w0=g_dinv[sn0]*dv, w1=g_dinv[sn1]*dv, w2=g_dinv[sn2]*dv, w3=g_dinv[sn3]*dv;
    a_s.x+=x0.x+x1.x+x2.x+x3.x; a_s.y+=x0.y+x1.y+x2.y+x3.y;
    a_s.z+=x0.z+x1.z+x2.z+x3.z; a_s.w+=x0.w+x1.w+x2.w+x3.w;
    a_n.x+=w0*x0.x+w1*x1.x+w2*x2.x+w3*x3.x; a_n.y+=w0*x0.y+w1*x1.y+w2*x2.y+w3*x3.y;
    a_n.z+=w0*x0.z+w1*x1.z+w2*x2.z+w3*x3.z; a_n.w+=w0*x0.w+w1*x1.w+w2*x2.w+w3*x3.w;
    a_a.x+=c0*x0.x+c1*x1.x+c2*x2.x+c3*x3.x; a_a.y+=c0*x0.y+c1*x1.y+c2*x2.y+c3*x3.y;
    a_a.z+=c0*x0.z+c1*x1.z+c2*x2.z+c3*x3.z; a_a.w+=c0*x0.w+c1*x1.w+c2*x2.w+c3*x3.w;
  }
  for (; j<e; j++){
    int sn = g_csrsrc[j];
    float ev = g_s0[sn] + s1v;
    ev = ev>0.f ? ev : 0.2f*ev;
    float ca = __expf(ev) * sinv;
    float nw = g_dinv[sn]*dv;
    float4 xv = ((const float4*)g_xw)[sn*32 + lane];
    a_s.x+=xv.x;      a_s.y+=xv.y;      a_s.z+=xv.z;      a_s.w+=xv.w;
    a_n.x+=nw*xv.x;   a_n.y+=nw*xv.y;   a_n.z+=nw*xv.z;   a_n.w+=nw*xv.w;
    a_a.x+=ca*xv.x;   a_a.y+=ca*xv.y;   a_a.z+=ca*xv.z;   a_a.w+=ca*xv.w;
  }
  ((float4*)g_sum)[w*32+lane]=a_s;
  ((float4*)g_nrm)[w*32+lane]=a_n;
  ((float4*)g_att)[w*32+lane]=a_a;
}

// ------------------------- warp-MMA mixed-op GEMM + LN + DARTS mix -------------------------
#define MT 64
#define PADK 136
#define SM_AHI 0
#define SM_ALO (MT*PADK*2)
#define SM_WHI (2*MT*PADK*2)
#define SM_WLO (SM_WHI + 128*PADK*2)
#define SM_BB  (SM_WLO + 128*PADK*2)
#define SM_LG  (SM_BB+512)
#define SM_LB  (SM_LG+512)
#define SMEM_MIX (SM_LB+512)

__constant__ int c_opseq[7] = {0,5,1,2,3,4,6};
__constant__ int c_asel[7]  = {0,0,1,2,3,4,5};

__global__ void __launch_bounds__(256,2) k_mix_mma(int l,
    const float* __restrict__ bops, const float* __restrict__ lng, const float* __restrict__ lnb){
  extern __shared__ char smc[];
  uint32_t sbase = smem_u32(smc);
  float* s_bb = (float*)(smc + SM_BB);
  float* s_lg = (float*)(smc + SM_LG);
  float* s_lb = (float*)(smc + SM_LB);
  int tid = threadIdx.x;
  int lane = tid & 31, w = tid >> 5;
  int wr = w & 3, wc = w >> 2;
  int g = lane >> 2, tig = lane & 3;
  int n0 = blockIdx.x * MT;
  if (tid < 128){ s_lg[tid] = lng[l*128+tid]; s_lb[tid] = lnb[l*128+tid]; }

  int a_off = ((lane&7) + ((lane>>3)&1)*8)*PADK + (lane>>4)*8;
  int b_off = (((lane>>4)&1)*8 + (lane&7))*PADK + ((lane>>3)&1)*8;
  uint32_t AbH = sbase + SM_AHI + (uint32_t)(wr*16*PADK + a_off)*2;
  uint32_t AbL = sbase + SM_ALO + (uint32_t)(wr*16*PADK + a_off)*2;
  uint32_t WbH = sbase + SM_WHI + (uint32_t)(wc*64*PADK)*2 + (uint32_t)b_off*2;
  uint32_t WbL = sbase + SM_WLO + (uint32_t)(wc*64*PADK)*2 + (uint32_t)b_off*2;

  float mix[8][4];
  #pragma unroll
  for (int f=0;f<8;f++){ mix[f][0]=0.f; mix[f][1]=0.f; mix[f][2]=0.f; mix[f][3]=0.f; }

  int prevA = -1;
  for (int oi=0; oi<7; oi++){
    int o = c_opseq[oi], asel = c_asel[oi];
    __syncthreads();
    // W tiles via cp.async — overlaps with A-build below
    {
      const uint4* srcH = (const uint4*)(g_Whi + (size_t)(l*NOPS+o)*16384);
      const uint4* srcL = (const uint4*)(g_Wlo + (size_t)(l*NOPS+o)*16384);
      #pragma unroll
      for (int it=0; it<8; it++){
        int i = it*256 + tid;
        int row = i >> 4, q = i & 15;
        uint32_t off = (uint32_t)(row*PADK + q*8)*2;
        cpa16(sbase + SM_WHI + off, srcH + i);
        cpa16(sbase + SM_WLO + off, srcL + i);
      }
      CPA_COMMIT();
    }
    if (asel != prevA){
      prevA = asel;
      #pragma unroll 2
      for (int it=0; it<16; it++){
        int wi = it*256 + tid;
        int r = wi >> 6;
        int h0 = (wi & 63)*2;
        int n = n0 + r;
        float vx=0.f, vy=0.f;
        if (n < NN){
          size_t base = (size_t)n*HH + h0;
          if (asel==0){ float2 a = *(const float2*)(g_nrm+base); vx=a.x; vy=a.y; }
          else if (asel==1){ float2 a=*(const float2*)(g_xw+base); float2 bq=*(const float2*)(g_sum+base); vx=a.x+bq.x; vy=a.y+bq.y; }
          else if (asel==2){ float2 a=*(const float2*)(g_att+base); vx=a.x; vy=a.y; }
          else if (asel==3){ float2 a=*(const float2*)(g_xw+base); float2 bq=*(const float2*)(g_sum+base); float m=g_minv[n]; vx=a.x+bq.x*m; vy=a.y+bq.y*m; }
          else if (asel==4){ float2 bq=*(const float2*)(g_sum+base); float m=g_minv[n]; vx=bq.x*m; vy=bq.y*m; }
          else { float2 a=*(const float2*)(g_xw+base); vx=a.x; vy=a.y; }
        }
        __nv_bfloat16 hx = __float2bfloat16(vx);
        __nv_bfloat16 hy = __float2bfloat16(vy);
        __nv_bfloat16 lx = __float2bfloat16(vx - __bfloat162float(hx));
        __nv_bfloat16 ly = __float2bfloat16(vy - __bfloat162float(hy));
        uint32_t off = (uint32_t)(r*PADK + h0)*2;
        *(uint32_t*)(smc + SM_AHI + off) = (uint32_t)__bfloat16_as_ushort(hx) | ((uint32_t)__bfloat16_as_ushort(hy)<<16);
        *(uint32_t*)(smc + SM_ALO + off) = (uint32_t)__bfloat16_as_ushort(lx) | ((uint32_t)__bfloat16_as_ushort(ly)<<16);
      }
    }
    if (tid < 128){
      int c = tid>>5, k = tid&31;
      s_bb[tid] = bops[((size_t)(l*CC + c)*NOPS + o)*KK + k];
    }
    CPA_WAIT();
    __syncthreads();

    float acc[8][4];
    #pragma unroll
    for (int f=0;f<8;f++){ acc[f][0]=0.f; acc[f][1]=0.f; acc[f][2]=0.f; acc[f][3]=0.f; }
    #pragma unroll 1
    for (int ks=0; ks<8; ks++){
      uint32_t k0b = (uint32_t)(ks*16)*2;
      uint32_t ah[4], al[4];
      ldsm4(ah[0],ah[1],ah[2],ah[3], AbH + k0b);
      ldsm4(al[0],al[1],al[2],al[3], AbL + k0b);
      #pragma unroll
      for (int nf=0; nf<4; nf++){
        uint32_t bh[4], bl[4];
        uint32_t woff = (uint32_t)(nf*16*PADK)*2 + k0b;
        ldsm4(bh[0],bh[1],bh[2],bh[3], WbH + woff);
        ldsm4(bl[0],bl[1],bl[2],bl[3], WbL + woff);
        mma16816(acc[2*nf],   ah, bh);
        mma16816(acc[2*nf],   ah, bl);
        mma16816(acc[2*nf],   al, bh);
        mma16816(acc[2*nf+1], ah, bh+2);
        mma16816(acc[2*nf+1], ah, bl+2);
        mma16816(acc[2*nf+1], al, bh+2);
      }
    }
    #pragma unroll
    for (int ch=0; ch<2; ch++){
      int c = wc*2 + ch;
      float tv[4][4];
      float sA=0.f, sqA=0.f, sB=0.f, sqB=0.f;
      #pragma unroll
      for (int fi=0; fi<4; fi++){
        int f = 4*ch + fi;
        int col0 = wc*64 + f*8 + 2*tig;
        float b0 = s_bb[col0], b1 = s_bb[col0+1];
        float t0 = acc[f][0]+b0, t1 = acc[f][1]+b1;
        float t2 = acc[f][2]+b0, t3 = acc[f][3]+b1;
        tv[fi][0]=t0; tv[fi][1]=t1; tv[fi][2]=t2; tv[fi][3]=t3;
        sA += t0+t1; sqA += t0*t0+t1*t1;
        sB += t2+t3; sqB += t2*t2+t3*t3;
      }
      sA += __shfl_xor_sync(0xffffffffu, sA, 1);  sqA += __shfl_xor_sync(0xffffffffu, sqA, 1);
      sB += __shfl_xor_sync(0xffffffffu, sB, 1);  sqB += __shfl_xor_sync(0xffffffffu, sqB, 1);
      sA += __shfl_xor_sync(0xffffffffu, sA, 2);  sqA += __shfl_xor_sync(0xffffffffu, sqA, 2);
      sB += __shfl_xor_sync(0xffffffffu, sB, 2);  sqB += __shfl_xor_sync(0xffffffffu, sqB, 2);
      float mA = sA*(1.f/32.f), vA = sqA*(1.f/32.f) - mA*mA;
      float mB = sB*(1.f/32.f), vB = sqB*(1.f/32.f) - mB*mB;
      float rA2 = rsqrtf(vA + 1e-5f), rB2 = rsqrtf(vB + 1e-5f);
      float wv = g_wmix[(l*CC + c)*NOPS + o];
      #pragma unroll
      for (int fi=0; fi<4; fi++){
        int f = 4*ch + fi;
        int col0 = wc*64 + f*8 + 2*tig;
        float lg0=s_lg[col0], lg1=s_lg[col0+1], lb0=s_lb[col0], lb1=s_lb[col0+1];
        mix[f][0] += wv*((tv[fi][0]-mA)*rA2*lg0 + lb0);
        mix[f][1] += wv*((tv[fi][1]-mA)*rA2*lg1 + lb1);
        mix[f][2] += wv*((tv[fi][2]-mB)*rB2*lg0 + lb0);
        mix[f][3] += wv*((tv[fi][3]-mB)*rB2*lg1 + lb1);
      }
    }
  }
  int rA = n0 + wr*16 + g;
  int rB = rA + 8;
  float* yout = g_gr + (size_t)(l+1)*NN*HH;
  #pragma unroll
  for (int f=0; f<8; f++){
    int col = wc*64 + f*8 + 2*tig;
    if (rA < NN) *(float2*)&yout[(size_t)rA*HH + col] = make_float2(mix[f][0], mix[f][1]);
    if (rB < NN) *(float2*)&yout[(size_t)rB*HH + col] = make_float2(mix[f][2], mix[f][3]);
  }
}

// ------------------------- BatchNorm stats (standalone, fused finisher) -------------------------
__global__ void k_bnstat(const float* __restrict__ bng, const float* __restrict__ bnb, int l){
  int t = threadIdx.x; int b = blockIdx.x;
  const float* y = g_gr + (size_t)(l+1)*NN*HH;
  float s=0.f, sq=0.f;
  for (int r=b; r<NN; r+=BNG){
    float v = y[(size_t)r*HH + t];
    s+=v; sq+=v*v;
  }
  g_part[b*HH+t]=s;
  g_part[BNG*HH + b*HH+t]=sq;
  __threadfence();
  __shared__ int lastS;
  if (t==0) lastS = (atomicAdd(&g_cbn,1) == BNG-1);
  __syncthreads();
  if (lastS){
    float ts=0.f, tq=0.f;
    for (int bb=0;bb<BNG;bb++){ ts+=g_part[bb*HH+t]; tq+=g_part[BNG*HH+bb*HH+t]; }
    float mean = ts*(1.f/NN);
    float var  = tq*(1.f/NN) - mean*mean;
    float sc = bng[l*HH+t]*rsqrtf(var+1e-5f);
    g_scA[(l+1)*HH+t] = sc;
    g_shA[(l+1)*HH+t] = bnb[l*HH+t]-mean*sc;
    if (t==0) g_cbn = 0;
  }
}

// ------------------------- virtual node MLP (vt fused into vnl1) -------------------------
__global__ void k_vnl1(const float* __restrict__ vn0,
                       const float* __restrict__ W1, const float* __restrict__ b1,
                       const float* __restrict__ bn_g, const float* __restrict__ bn_b, int l){
  __shared__ float vp[2][HH];
  __shared__ float vr[HH];
  __shared__ int lastS;
  int row=blockIdx.x, t=threadIdx.x;
  int s=g_bstart[row], e=g_bstart[row+1];
  {
    int half = t>>7, col = t&127;
    float acc=0.f;
    const float* gp = g_gr + (size_t)(l+1)*NN*HH;
    for (int r=s+half; r<e; r+=2) acc += gp[(size_t)r*HH+col];
    vp[half][col]=acc;
  }
  __syncthreads();
  if (t < HH){
    float sc = g_scA[(l+1)*HH+t], sh = g_shA[(l+1)*HH+t];
    float acc = (vp[0][t]+vp[1][t])*sc + (float)(e-s)*sh;
    float vnv;
    if (l == 0) vnv = vn0[t];
    else { float v = g_h2[row*HH+t]*g_sc2[t]+g_sh2[t]; vnv = v>0.f? v:0.f; }
    vr[t] = acc + vnv;
  }
  __syncthreads();
  float acc = b1[l*2*HH+t];
  const float* wp = W1 + (size_t)l*HH*2*HH + t;
  #pragma unroll 4
  for (int h=0;h<HH;h++) acc += vr[h]*wp[h*2*HH];
  g_h1[row*2*HH+t]=acc;
  __threadfence();
  if (t==0) lastS = (atomicAdd(&g_c1,1) == NB-1);
  __syncthreads();
  if (lastS){
    float s2=0.f, sq=0.f;
    for (int r=0;r<NB;r++){ float v=g_h1[r*2*HH+t]; s2+=v; sq+=v*v; }
    float mean=s2*(1.f/NB);
    float var=sq*(1.f/NB)-mean*mean;
    float sc = bn_g[l*2*HH+t]*rsqrtf(var+1e-5f);
    g_sc1[t]=sc;
    g_sh1[t]=bn_b[l*2*HH+t]-mean*sc;
    if (t==0) g_c1 = 0;
  }
}
__global__ void k_vnl2(const float* __restrict__ W2, const float* __restrict__ b2,
                       const float* __restrict__ bn_g, const float* __restrict__ bn_b, int l){
  __shared__ float hr[2*HH];
  __shared__ int lastS;
  int row=blockIdx.x, t=threadIdx.x;
  {
    float v0 = g_h1[row*2*HH+t]*g_sc1[t]+g_sh1[t];
    float v1 = g_h1[row*2*HH+t+HH]*g_sc1[t+HH]+g_sh1[t+HH];
    hr[t]    = v0>0.f? v0:0.f;
    hr[t+HH] = v1>0.f? v1:0.f;
  }
  __syncthreads();
  float acc = b2[l*HH+t];
  const float* wp = W2 + (size_t)l*2*HH*HH + t;
  #pragma unroll 4
  for (int h=0;h<2*HH;h++) acc += hr[h]*wp[h*HH];
  g_h2[row*HH+t]=acc;
  __threadfence();
  if (t==0) lastS = (atomicAdd(&g_c2,1) == NB-1);
  __syncthreads();
  if (lastS){
    float s=0.f, sq=0.f;
    for (int r=0;r<NB;r++){ float v=g_h2[r*HH+t]; s+=v; sq+=v*v; }
    float mean=s*(1.f/NB);
    float var=sq*(1.f/NB)-mean*mean;
    float sc = bn_g[l*HH+t]*rsqrtf(var+1e-5f);
    g_sc2[t]=sc;
    g_sh2[t]=bn_b[l*HH+t]-mean*sc;
    if (t==0) g_c2 = 0;
  }
}

// ------------------------- pooling + head (stage-parallel pool) -------------------------
__global__ void k_pool(){
  int b=blockIdx.x, st=blockIdx.y, t=threadIdx.x;
  int s=g_bstart[b], e=g_bstart[b+1];
  float inv = 1.f/(float)max(e-s,1);
  const float* gp = g_gr + (size_t)st*NN*HH;
  float sc = g_scA[st*HH+t], sh = g_shA[st*HH+t];
  float sum=0.f, mx=-1e30f;
  for (int r=s;r<e;r++){
    float v=gp[(size_t)r*HH+t]*sc+sh;
    sum+=v; mx=fmaxf(mx,v);
  }
  if (e==s) mx=0.f;
  g_pooled[b*1024 + st*HH + t] = sum*inv;
  g_pooled[b*1024 + 512 + st*HH + t] = mx;
}
__global__ void k_head(const float* __restrict__ hW, const float* __restrict__ hb,
                       const float* __restrict__ hM, float* __restrict__ out){
  __shared__ float red[NOUT];
  int b=blockIdx.x, t=threadIdx.x;
  if (t<NOUT) red[t]=0.f;
  __syncthreads();
  float acc[NOUT];
  #pragma unroll
  for (int j=0;j<NOUT;j++) acc[j]=0.f;
  for (int d=t; d<1024; d+=256){
    float pv = g_pooled[b*1024+d];
    const float* wrow = hW + d*NOUT;
    const float* mrow = hM + d*NOUT;
    #pragma unroll
    for (int j=0;j<NOUT;j++) acc[j] += pv*wrow[j]*mrow[j];
  }
  #pragma unroll
  for (int j=0;j<NOUT;j++) atomicAdd(&red[j], acc[j]);
  __syncthreads();
  if (t<NOUT) out[b*NOUT+t] = red[t] + hb[t];
}

// ------------------------- launch -------------------------
extern "C" void kernel_launch(void* const* d_in, const int* in_sizes, int n_in,
                              void* d_out, int out_size){
  const float* x      = (const float*)d_in[0];
  const int*   ei     = (const int*)d_in[1];
  const int*   batch  = (const int*)d_in[2];
  const float* lin1W  = (const float*)d_in[3];
  const float* lin1b  = (const float*)d_in[4];
  const float* vn0    = (const float*)d_in[5];
  const float* Wops   = (const float*)d_in[6];
  const float* bops   = (const float*)d_in[7];
  const float* atta   = (const float*)d_in[8];
  const float* lng    = (const float*)d_in[9];
  const float* lnb    = (const float*)d_in[10];
  const float* bng    = (const float*)d_in[11];
  const float* bnb    = (const float*)d_in[12];
  const float* vnW1   = (const float*)d_in[13];
  const float* vnb1   = (const float*)d_in[14];
  const float* vnbn1g = (const float*)d_in[15];
  const float* vnbn1b = (const float*)d_in[16];
  const float* vnW2   = (const float*)d_in[17];
  const float* vnb2   = (const float*)d_in[18];
  const float* vnbn2g = (const float*)d_in[19];
  const float* vnbn2b = (const float*)d_in[20];
  const float* alphas = (const float*)d_in[21];
  const float* headW  = (const float*)d_in[22];
  const float* headb  = (const float*)d_in[23];
  const float* headM  = (const float*)d_in[24];
  float* out = (float*)d_out;
  const int* src = ei;
  const int* dst = ei + NE;

  cudaFuncSetAttribute(k_mix_mma, cudaFuncAttributeMaxDynamicSharedMemorySize, SMEM_MIX);
  cudaFuncSetAttribute(k_lin1_mma, cudaFuncAttributeMaxDynamicSharedMemorySize, SMEM_L1);

  const int NBLK = (NN + 255)/256;
  const int WBLK = (NN*32 + 255)/256;
  const int EBLK = (NE + 255)/256;
  const int MIXBLK = (NN + MT-1)/MT;   // 782

  k_zero_deg<<<NBLK,256>>>();
  k_count<<<EBLK,256>>>(dst);
  k_scan<<<1,1024>>>();
  k_wprep1<<<(128*64+255)/256,256>>>(lin1W);
  k_wprep<<<(LL*NOPS*16384+255)/256,256>>>(Wops);
  k_lin1_mma<<<MIXBLK,256,SMEM_L1>>>(x, lin1b);
  k_scatter<<<EBLK,256>>>(src, dst);
  k_bstart<<<NBLK,256>>>(batch);
  k_prepw<<<1,128>>>(alphas);

  for (int l=0; l<LL; l++){
    k_nodeA<<<WBLK,256>>>(batch, atta, vn0, l);
    k_edge<<<WBLK,256>>>();
    k_mix_mma<<<MIXBLK,256,SMEM_MIX>>>(l, bops, lng, lnb);
    k_bnstat<<<BNG,128>>>(bng, bnb, l);
    if (l < LL-1){
      k_vnl1<<<NB,256>>>(vn0, vnW1, vnb1, vnbn1g, vnbn1b, l);
      k_vnl2<<<NB,128>>>(vnW2, vnb2, vnbn2g, vnbn2b, l);
    }
  }
  k_pool<<<dim3(NB,4),128>>>();
  k_head<<<NB,256>>>(headW, headb, headM, out);
}

// round 16
// speedup vs baseline: 1.1029x; 1.0003x over previous
#include <cuda_runtime.h>
#include <cuda_bf16.h>
#include <math.h>
#include <stdint.h>

#define NN 50000
#define NE 800000
#define FIN 64
#define HH 128
#define LL 3
#define CC 4
#define KK 32
#define NOPS 7
#define NB 512
#define NOUT 10
#define BNG 400

// ------------------------- device scratch (no allocs) -------------------------
__device__ float g_gr[(LL+1)*NN*HH];
__device__ float g_xw[NN*HH];
__device__ float g_sum[NN*HH];
__device__ float g_nrm[NN*HH];
__device__ float g_att[NN*HH];
__device__ float g_s0[NN];
__device__ float g_s1[NN];
__device__ float g_dinv[NN];
__device__ float g_minv[NN];
__device__ int   g_deg[NN];
__device__ int   g_rowptr[NN+1];
__device__ int   g_cursor[NN];
__device__ int   g_csrsrc[NE];
__device__ int   g_bstart[NB+1];
__device__ float g_wmix[LL*CC*NOPS];
__device__ float g_h1[NB*2*HH];
__device__ float g_h2[NB*HH];
__device__ float g_scA[(LL+1)*HH];
__device__ float g_shA[(LL+1)*HH];
__device__ float g_sc1[2*HH];
__device__ float g_sh1[2*HH];
__device__ float g_sc2[HH];
__device__ float g_sh2[HH];
__device__ float g_part[2*BNG*HH];
__device__ float g_pooled[NB*8*HH];
__device__ int   g_cbn = 0;
__device__ int   g_c1 = 0;
__device__ int   g_c2 = 0;
__device__ unsigned short g_Whi[LL*NOPS*16384];
__device__ unsigned short g_Wlo[LL*NOPS*16384];
__device__ unsigned short g_W1hi[128*64];
__device__ unsigned short g_W1lo[128*64];

// ------------------------- PTX helpers (baseline ISA, sm_80+) -------------------------
__device__ __forceinline__ uint32_t smem_u32(const void* p){
  uint32_t a; asm("{ .reg .u64 t; cvta.to.shared.u64 t, %1; cvt.u32.u64 %0, t; }" : "=r"(a) : "l"(p));
  return a;
}
__device__ __forceinline__ void ldsm4(uint32_t &r0, uint32_t &r1, uint32_t &r2, uint32_t &r3, uint32_t addr){
  asm volatile("ldmatrix.sync.aligned.m8n8.x4.shared.b16 {%0,%1,%2,%3}, [%4];"
    : "=r"(r0), "=r"(r1), "=r"(r2), "=r"(r3) : "r"(addr));
}
__device__ __forceinline__ void mma16816(float* d, const uint32_t* a, const uint32_t* b){
  asm volatile("mma.sync.aligned.m16n8k16.row.col.f32.bf16.bf16.f32 "
    "{%0,%1,%2,%3}, {%4,%5,%6,%7}, {%8,%9}, {%0,%1,%2,%3};"
    : "+f"(d[0]), "+f"(d[1]), "+f"(d[2]), "+f"(d[3])
    : "r"(a[0]), "r"(a[1]), "r"(a[2]), "r"(a[3]), "r"(b[0]), "r"(b[1]));
}
__device__ __forceinline__ void cpa16(uint32_t saddr, const void* gaddr){
  asm volatile("cp.async.cg.shared.global [%0], [%1], 16;" :: "r"(saddr), "l"(gaddr));
}
#define CPA_COMMIT() asm volatile("cp.async.commit_group;" ::: "memory")
#define CPA_WAIT()   asm volatile("cp.async.wait_group 0;" ::: "memory")

// ------------------------- CSR build -------------------------
__global__ void k_zero_deg(){
  int i = blockIdx.x*blockDim.x + threadIdx.x;
  if (i < NN) g_deg[i] = 0;
}
__global__ void k_count(const int* __restrict__ dst){
  int e = blockIdx.x*blockDim.x + threadIdx.x;
  if (e < NE) atomicAdd(&g_deg[dst[e]], 1);
}
__global__ void k_scan(){
  __shared__ int sm[1024];
  const int CH = (NN + 1023)/1024;
  int t = threadIdx.x;
  int s = 0;
  for (int i=0;i<CH;i++){ int idx = t*CH+i; if (idx<NN) s += g_deg[idx]; }
  sm[t] = s; __syncthreads();
  for (int off=1; off<1024; off<<=1){
    int v = (t>=off) ? sm[t-off] : 0;
    __syncthreads();
    if (t>=off) sm[t] += v;
    __syncthreads();
  }
  int run = (t>0)? sm[t-1] : 0;
  for (int i=0;i<CH;i++){
    int idx=t*CH+i;
    if (idx<NN){
      g_rowptr[idx]=run;
      g_cursor[idx]=run;
      int d = g_deg[idx];
      run += d;
      float dc = (float)max(d, 1);
      g_dinv[idx] = rsqrtf(dc);
      g_minv[idx] = 1.f/dc;
    }
  }
  if (t==1023) g_rowptr[NN] = sm[1023];
}
__global__ void k_scatter(const int* __restrict__ src, const int* __restrict__ dst){
  int e = blockIdx.x*blockDim.x + threadIdx.x;
  if (e < NE){
    int slot = atomicAdd(&g_cursor[dst[e]], 1);
    g_csrsrc[slot] = src[e];
  }
}
__global__ void k_bstart(const int* __restrict__ batch){
  int i = blockIdx.x*blockDim.x + threadIdx.x;
  if (i >= NN) return;
  int b = batch[i];
  if (i == 0){ for (int bb=0; bb<=b; bb++) g_bstart[bb] = 0; }
  else { int p = batch[i-1]; for (int bb=p+1; bb<=b; bb++) g_bstart[bb] = i; }
  if (i == NN-1){ for (int bb=b+1; bb<=NB; bb++) g_bstart[bb] = NN; }
}
__global__ void k_prepw(const float* __restrict__ alphas){
  int g = threadIdx.x;
  if (g < 128){ g_scA[g] = 1.f; g_shA[g] = 0.f; }
  if (g < LL*CC){
    const float* a = alphas + g*NOPS;
    float mx = a[0];
    for (int o=1;o<NOPS;o++) mx = fmaxf(mx, a[o]);
    float e[NOPS]; float s = 0.f;
    for (int o=0;o<NOPS;o++){ e[o] = expf(a[o]-mx); s += e[o]; }
    for (int o=0;o<NOPS;o++) g_wmix[g*NOPS+o] = e[o]/s;
  }
}

// ------------------------- weight prep -------------------------
__global__ void k_wprep(const float* __restrict__ Wops){
  int idx = blockIdx.x*blockDim.x + threadIdx.x;
  if (idx >= LL*NOPS*16384) return;
  int lop = idx >> 14;
  int el  = idx & 16383;
  int l = lop / NOPS, o = lop % NOPS;
  int r = el >> 7;
  int h = el & 127;
  int c = r >> 5, k = r & 31;
  float w = Wops[(((size_t)(l*CC + c)*NOPS + o)*HH + h)*KK + k];
  __nv_bfloat16 hb = __float2bfloat16(w);
  float res = w - __bfloat162float(hb);
  __nv_bfloat16 lb = __float2bfloat16(res);
  g_Whi[(size_t)lop*16384 + r*128 + h] = __bfloat16_as_ushort(hb);
  g_Wlo[(size_t)lop*16384 + r*128 + h] = __bfloat16_as_ushort(lb);
}
__global__ void k_wprep1(const float* __restrict__ W){
  int idx = blockIdx.x*blockDim.x + threadIdx.x;
  if (idx >= 128*64) return;
  int r = idx >> 6, h = idx & 63;
  float w = W[h*128 + r];
  __nv_bfloat16 hb = __float2bfloat16(w);
  float res = w - __bfloat162float(hb);
  __nv_bfloat16 lb = __float2bfloat16(res);
  g_W1hi[r*64+h] = __bfloat16_as_ushort(hb);
  g_W1lo[r*64+h] = __bfloat16_as_ushort(lb);
}

// ------------------------- lin1 + ELU via warp MMA -------------------------
#define PADK1 72
#define L1_AHI 0
#define L1_ALO (64*PADK1*2)
#define L1_WHI (2*64*PADK1*2)
#define L1_WLO (L1_WHI + 128*PADK1*2)
#define L1_BB  (L1_WLO + 128*PADK1*2)
#define SMEM_L1 (L1_BB + 512)

__global__ void __launch_bounds__(256,3) k_lin1_mma(const float* __restrict__ x,
    const float* __restrict__ bias){
  extern __shared__ char smc[];
  uint32_t sbase = smem_u32(smc);
  float* s_b1 = (float*)(smc + L1_BB);
  int tid = threadIdx.x;
  int lane = tid & 31, w = tid >> 5;
  int wr = w & 3, wc = w >> 2;
  int g = lane >> 2, tig = lane & 3;
  int n0 = blockIdx.x * 64;
  if (tid < 128) s_b1[tid] = bias[tid];

  #pragma unroll 1
  for (int it=0; it<8; it++){
    int wi = it*256 + tid;
    int r = wi >> 5;
    int h0 = (wi & 31)*2;
    int n = n0 + r;
    float vx=0.f, vy=0.f;
    if (n < NN){
      float2 a = *(const float2*)(x + (size_t)n*FIN + h0);
      vx=a.x; vy=a.y;
    }
    __nv_bfloat16 hx = __float2bfloat16(vx);
    __nv_bfloat16 hy = __float2bfloat16(vy);
    __nv_bfloat16 lx = __float2bfloat16(vx - __bfloat162float(hx));
    __nv_bfloat16 ly = __float2bfloat16(vy - __bfloat162float(hy));
    uint32_t off = (uint32_t)(r*PADK1 + h0)*2;
    *(uint32_t*)(smc + L1_AHI + off) = (uint32_t)__bfloat16_as_ushort(hx) | ((uint32_t)__bfloat16_as_ushort(hy)<<16);
    *(uint32_t*)(smc + L1_ALO + off) = (uint32_t)__bfloat16_as_ushort(lx) | ((uint32_t)__bfloat16_as_ushort(ly)<<16);
  }
  {
    const uint4* srcH = (const uint4*)g_W1hi;
    const uint4* srcL = (const uint4*)g_W1lo;
    #pragma unroll
    for (int it=0; it<4; it++){
      int i = it*256 + tid;
      int row = i >> 3, q = i & 7;
      uint32_t off = (uint32_t)(row*PADK1 + q*8)*2;
      *(uint4*)(smc + L1_WHI + off) = srcH[i];
      *(uint4*)(smc + L1_WLO + off) = srcL[i];
    }
  }
  __syncthreads();

  int a_off = ((lane&7) + ((lane>>3)&1)*8)*PADK1 + (lane>>4)*8;
  int b_off = (((lane>>4)&1)*8 + (lane&7))*PADK1 + ((lane>>3)&1)*8;
  uint32_t AbH = sbase + L1_AHI + (uint32_t)(wr*16*PADK1 + a_off)*2;
  uint32_t AbL = sbase + L1_ALO + (uint32_t)(wr*16*PADK1 + a_off)*2;
  uint32_t WbH = sbase + L1_WHI + (uint32_t)(wc*64*PADK1 + b_off)*2;
  uint32_t WbL = sbase + L1_WLO + (uint32_t)(wc*64*PADK1 + b_off)*2;

  float acc[8][4];
  #pragma unroll
  for (int f=0;f<8;f++){ acc[f][0]=0.f; acc[f][1]=0.f; acc[f][2]=0.f; acc[f][3]=0.f; }
  #pragma unroll
  for (int ks=0; ks<4; ks++){
    uint32_t k0b = (uint32_t)(ks*16)*2;
    uint32_t ah[4], al[4];
    ldsm4(ah[0],ah[1],ah[2],ah[3], AbH + k0b);
    ldsm4(al[0],al[1],al[2],al[3], AbL + k0b);
    #pragma unroll
    for (int nf=0; nf<4; nf++){
      uint32_t bh[4], bl[4];
      uint32_t woff = (uint32_t)(nf*16*PADK1)*2 + k0b;
      ldsm4(bh[0],bh[1],bh[2],bh[3], WbH + woff);
      ldsm4(bl[0],bl[1],bl[2],bl[3], WbL + woff);
      mma16816(acc[2*nf],   ah, bh);
      mma16816(acc[2*nf],   ah, bl);
      mma16816(acc[2*nf],   al, bh);
      mma16816(acc[2*nf+1], ah, bh+2);
      mma16816(acc[2*nf+1], ah, bl+2);
      mma16816(acc[2*nf+1], al, bh+2);
    }
  }
  int rA = n0 + wr*16 + g;
  int rB = rA + 8;
  #pragma unroll
  for (int f=0; f<8; f++){
    int col = wc*64 + f*8 + 2*tig;
    float b0 = s_b1[col], b1 = s_b1[col+1];
    float t0 = acc[f][0]+b0, t1 = acc[f][1]+b1;
    float t2 = acc[f][2]+b0, t3 = acc[f][3]+b1;
    t0 = t0>0.f ? t0 : expm1f(t0);
    t1 = t1>0.f ? t1 : expm1f(t1);
    t2 = t2>0.f ? t2 : expm1f(t2);
    t3 = t3>0.f ? t3 : expm1f(t3);
    if (rA < NN) *(float2*)&g_gr[(size_t)rA*HH + col] = make_float2(t0, t1);
    if (rB < NN) *(float2*)&g_gr[(size_t)rB*HH + col] = make_float2(t2, t3);
  }
}

// ------------------------- per-layer node prep (lazy BN affine + lazy vn) -------------------------
__global__ void k_nodeA(const int* __restrict__ batch, const float* __restrict__ atta,
                        const float* __restrict__ vn0, int l){
  int w = (blockIdx.x*blockDim.x + threadIdx.x) >> 5;
  int lane = threadIdx.x & 31;
  if (w >= NN) return;
  int b = batch[w];
  float4 xv = ((const float4*)(g_gr + (size_t)l*NN*HH))[w*32 + lane];
  float4 sc = ((const float4*)(g_scA + l*HH))[lane];
  float4 sh = ((const float4*)(g_shA + l*HH))[lane];
  xv.x = xv.x*sc.x+sh.x; xv.y = xv.y*sc.y+sh.y; xv.z = xv.z*sc.z+sh.z; xv.w = xv.w*sc.w+sh.w;
  float4 vv;
  if (l == 0){
    vv = ((const float4*)vn0)[lane];
  } else {
    float4 h2 = ((const float4*)g_h2)[b*32 + lane];
    float4 c2 = ((const float4*)g_sc2)[lane];
    float4 d2 = ((const float4*)g_sh2)[lane];
    vv.x = fmaxf(h2.x*c2.x+d2.x, 0.f);
    vv.y = fmaxf(h2.y*c2.y+d2.y, 0.f);
    vv.z = fmaxf(h2.z*c2.z+d2.z, 0.f);
    vv.w = fmaxf(h2.w*c2.w+d2.w, 0.f);
  }
  xv.x += vv.x; xv.y += vv.y; xv.z += vv.z; xv.w += vv.w;
  ((float4*)g_xw)[w*32 + lane] = xv;
  float4 a0 = ((const float4*)(atta + l*2*HH))[lane];
  float4 a1 = ((const float4*)(atta + l*2*HH + HH))[lane];
  float s0 = xv.x*a0.x + xv.y*a0.y + xv.z*a0.z + xv.w*a0.w;
  float s1 = xv.x*a1.x + xv.y*a1.y + xv.z*a1.z + xv.w*a1.w;
  #pragma unroll
  for (int off=16; off; off>>=1){
    s0 += __shfl_xor_sync(0xffffffffu, s0, off);
    s1 += __shfl_xor_sync(0xffffffffu, s1, off);
  }
  if (lane==0){ g_s0[w]=s0; g_s1[w]=s1; }
}

// ------------------------- fused attention + aggregation (warp per node) -------------------------
__global__ void k_edge(){
  int w = (blockIdx.x*blockDim.x + threadIdx.x) >> 5;
  int lane = threadIdx.x & 31;
  if (w >= NN) return;
  int s = g_rowptr[w], e = g_rowptr[w+1];
  float s1v = g_s1[w];
  float dv = g_dinv[w];
  float ss = 0.f;
  for (int j=s+lane; j<e; j+=32){
    float ev = g_s0[g_csrsrc[j]] + s1v;
    ev = ev>0.f ? ev : 0.2f*ev;
    ss += __expf(ev);
  }
  #pragma unroll
  for (int off=16; off; off>>=1) ss += __shfl_xor_sync(0xffffffffu, ss, off);
  float sinv = 1.f/(ss + 1e-16f);
  float4 a_s = make_float4(0.f,0.f,0.f,0.f);
  float4 a_n = a_s, a_a = a_s;
  int j = s;
  for (; j+4<=e; j+=4){
    int sn0=g_csrsrc[j], sn1=g_csrsrc[j+1], sn2=g_csrsrc[j+2], sn3=g_csrsrc[j+3];
    float4 x0 = ((const float4*)g_xw)[sn0*32 + lane];
    float4 x1 = ((const float4*)g_xw)[sn1*32 + lane];
    float4 x2 = ((const float4*)g_xw)[sn2*32 + lane];
    float4 x3 = ((const float4*)g_xw)[sn3*32 + lane];
    float e0=g_s0[sn0]+s1v, e1=g_s0[sn1]+s1v, e2=g_s0[sn2]+s1v, e3=g_s0[sn3]+s1v;
    e0 = e0>0.f? e0:0.2f*e0; e1 = e1>0.f? e1:0.2f*e1;
    e2 = e2>0.f? e2:0.2f*e2; e3 = e3>0.f? e3:0.2f*e3;
    float c0=__expf(e0)*sinv, c1=__expf(e1)*sinv, c2=__expf(e2)*sinv, c3=__expf(e3)*sinv;
    float w0=g_dinv[sn0]*dv, w1=g_dinv[sn1]*dv, w2=g_dinv[sn2]*dv, w3=g_dinv[sn3]*dv;
    a_s.x+=x0.x+x1.x+x2.x+x3.x; a_s.y+=x0.y+x1.y+x2.y+x3.y;
    a_s.z+=x0.z+x1.z+x2.z+x3.z; a_s.w+=x0.w+x1.w+x2.w+x3.w;
    a_n.x+=w0*x0.x+w1*x1.x+w2*x2.x+w3*x3.x; a_n.y+=w0*x0.y+w1*x1.y+w2*x2.y+w3*x3.y;
    a_n.z+=w0*x0.z+w1*x1.z+w2*x2.z+w3*x3.z; a_n.w+=w0*x0.w+w1*x1.w+w2*x2.w+w3*x3.w;
    a_a.x+=c0*x0.x+c1*x1.x+c2*x2.x+c3*x3.x; a_a.y+=c0*x0.y+c1*x1.y+c2*x2.y+c3*x3.y;
    a_a.z+=c0*x0.z+c1*x1.z+c2*x2.z+c3*x3.z; a_a.w+=c0*x0.w+c1*x1.w+c2*x2.w+c3*x3.w;
  }
  for (; j<e; j++){
    int sn = g_csrsrc[j];
    float ev = g_s0[sn] + s1v;
    ev = ev>0.f ? ev : 0.2f*ev;
    float ca = __expf(ev) * sinv;
    float nw = g_dinv[sn]*dv;
    float4 xv = ((const float4*)g_xw)[sn*32 + lane];
    a_s.x+=xv.x;      a_s.y+=xv.y;      a_s.z+=xv.z;      a_s.w+=xv.w;
    a_n.x+=nw*xv.x;   a_n.y+=nw*xv.y;   a_n.z+=nw*xv.z;   a_n.w+=nw*xv.w;
    a_a.x+=ca*xv.x;   a_a.y+=ca*xv.y;   a_a.z+=ca*xv.z;   a_a.w+=ca*xv.w;
  }
  ((float4*)g_sum)[w*32+lane]=a_s;
  ((float4*)g_nrm)[w*32+lane]=a_n;
  ((float4*)g_att)[w*32+lane]=a_a;
}

// ------------------------- warp-MMA mixed-op GEMM + LN + DARTS mix -------------------------
#define MT 64
#define PADK 136
#define SM_AHI 0
#define SM_ALO (MT*PADK*2)
#define SM_WHI (2*MT*PADK*2)
#define SM_WLO (SM_WHI + 128*PADK*2)
#define SM_BB  (SM_WLO + 128*PADK*2)
#define SM_LG  (SM_BB+512)
#define SM_LB  (SM_LG+512)
#define SMEM_MIX (SM_LB+512)

__constant__ int c_opseq[7] = {0,5,1,2,3,4,6};
__constant__ int c_asel[7]  = {0,0,1,2,3,4,5};

__global__ void __launch_bounds__(256,2) k_mix_mma(int l,
    const float* __restrict__ bops, const float* __restrict__ lng, const float* __restrict__ lnb){
  extern __shared__ char smc[];
  uint32_t sbase = smem_u32(smc);
  float* s_bb = (float*)(smc + SM_BB);
  float* s_lg = (float*)(smc + SM_LG);
  float* s_lb = (float*)(smc + SM_LB);
  int tid = threadIdx.x;
  int lane = tid & 31, w = tid >> 5;
  int wr = w & 3, wc = w >> 2;
  int g = lane >> 2, tig = lane & 3;
  int n0 = blockIdx.x * MT;
  if (tid < 128){ s_lg[tid] = lng[l*128+tid]; s_lb[tid] = lnb[l*128+tid]; }

  int a_off = ((lane&7) + ((lane>>3)&1)*8)*PADK + (lane>>4)*8;
  int b_off = (((lane>>4)&1)*8 + (lane&7))*PADK + ((lane>>3)&1)*8;
  uint32_t AbH = sbase + SM_AHI + (uint32_t)(wr*16*PADK + a_off)*2;
  uint32_t AbL = sbase + SM_ALO + (uint32_t)(wr*16*PADK + a_off)*2;
  uint32_t WbH = sbase + SM_WHI + (uint32_t)(wc*64*PADK)*2 + (uint32_t)b_off*2;
  uint32_t WbL = sbase + SM_WLO + (uint32_t)(wc*64*PADK)*2 + (uint32_t)b_off*2;

  float mix[8][4];
  #pragma unroll
  for (int f=0;f<8;f++){ mix[f][0]=0.f; mix[f][1]=0.f; mix[f][2]=0.f; mix[f][3]=0.f; }

  int prevA = -1;
  for (int oi=0; oi<7; oi++){
    int o = c_opseq[oi], asel = c_asel[oi];
    __syncthreads();
    // W tiles via cp.async — overlaps with A-build below
    {
      const uint4* srcH = (const uint4*)(g_Whi + (size_t)(l*NOPS+o)*16384);
      const uint4* srcL = (const uint4*)(g_Wlo + (size_t)(l*NOPS+o)*16384);
      #pragma unroll
      for (int it=0; it<8; it++){
        int i = it*256 + tid;
        int row = i >> 4, q = i & 15;
        uint32_t off = (uint32_t)(row*PADK + q*8)*2;
        cpa16(sbase + SM_WHI + off, srcH + i);
        cpa16(sbase + SM_WLO + off, srcL + i);
      }
      CPA_COMMIT();
    }
    if (asel != prevA){
      prevA = asel;
      #pragma unroll 4
      for (int it=0; it<16; it++){
        int wi = it*256 + tid;
        int r = wi >> 6;
        int h0 = (wi & 63)*2;
        int n = n0 + r;
        float vx=0.f, vy=0.f;
        if (n < NN){
          size_t base = (size_t)n*HH + h0;
          if (asel==0){ float2 a = *(const float2*)(g_nrm+base); vx=a.x; vy=a.y; }
          else if (asel==1){ float2 a=*(const float2*)(g_xw+base); float2 bq=*(const float2*)(g_sum+base); vx=a.x+bq.x; vy=a.y+bq.y; }
          else if (asel==2){ float2 a=*(const float2*)(g_att+base); vx=a.x; vy=a.y; }
          else if (asel==3){ float2 a=*(const float2*)(g_xw+base); float2 bq=*(const float2*)(g_sum+base); float m=g_minv[n]; vx=a.x+bq.x*m; vy=a.y+bq.y*m; }
          else if (asel==4){ float2 bq=*(const float2*)(g_sum+base); float m=g_minv[n]; vx=bq.x*m; vy=bq.y*m; }
          else { float2 a=*(const float2*)(g_xw+base); vx=a.x; vy=a.y; }
        }
        __nv_bfloat16 hx = __float2bfloat16(vx);
        __nv_bfloat16 hy = __float2bfloat16(vy);
        __nv_bfloat16 lx = __float2bfloat16(vx - __bfloat162float(hx));
        __nv_bfloat16 ly = __float2bfloat16(vy - __bfloat162float(hy));
        uint32_t off = (uint32_t)(r*PADK + h0)*2;
        *(uint32_t*)(smc + SM_AHI + off) = (uint32_t)__bfloat16_as_ushort(hx) | ((uint32_t)__bfloat16_as_ushort(hy)<<16);
        *(uint32_t*)(smc + SM_ALO + off) = (uint32_t)__bfloat16_as_ushort(lx) | ((uint32_t)__bfloat16_as_ushort(ly)<<16);
      }
    }
    if (tid < 128){
      int c = tid>>5, k = tid&31;
      s_bb[tid] = bops[((size_t)(l*CC + c)*NOPS + o)*KK + k];
    }
    CPA_WAIT();
    __syncthreads();

    float acc[8][4];
    #pragma unroll
    for (int f=0;f<8;f++){ acc[f][0]=0.f; acc[f][1]=0.f; acc[f][2]=0.f; acc[f][3]=0.f; }
    #pragma unroll 1
    for (int ks=0; ks<8; ks++){
      uint32_t k0b = (uint32_t)(ks*16)*2;
      uint32_t ah[4], al[4];
      ldsm4(ah[0],ah[1],ah[2],ah[3], AbH + k0b);
      ldsm4(al[0],al[1],al[2],al[3], AbL + k0b);
      #pragma unroll
      for (int nf=0; nf<4; nf++){
        uint32_t bh[4], bl[4];
        uint32_t woff = (uint32_t)(nf*16*PADK)*2 + k0b;
        ldsm4(bh[0],bh[1],bh[2],bh[3], WbH + woff);
        ldsm4(bl[0],bl[1],bl[2],bl[3], WbL + woff);
        mma16816(acc[2*nf],   ah, bh);
        mma16816(acc[2*nf],   ah, bl);
        mma16816(acc[2*nf],   al, bh);
        mma16816(acc[2*nf+1], ah, bh+2);
        mma16816(acc[2*nf+1], ah, bl+2);
        mma16816(acc[2*nf+1], al, bh+2);
      }
    }
    #pragma unroll
    for (int ch=0; ch<2; ch++){
      int c = wc*2 + ch;
      float tv[4][4];
      float sA=0.f, sqA=0.f, sB=0.f, sqB=0.f;
      #pragma unroll
      for (int fi=0; fi<4; fi++){
        int f = 4*ch + fi;
        int col0 = wc*64 + f*8 + 2*tig;
        float b0 = s_bb[col0], b1 = s_bb[col0+1];
        float t0 = acc[f][0]+b0, t1 = acc[f][1]+b1;
        float t2 = acc[f][2]+b0, t3 = acc[f][3]+b1;
        tv[fi][0]=t0; tv[fi][1]=t1; tv[fi][2]=t2; tv[fi][3]=t3;
        sA += t0+t1; sqA += t0*t0+t1*t1;
        sB += t2+t3; sqB += t2*t2+t3*t3;
      }
      sA += __shfl_xor_sync(0xffffffffu, sA, 1);  sqA += __shfl_xor_sync(0xffffffffu, sqA, 1);
      sB += __shfl_xor_sync(0xffffffffu, sB, 1);  sqB += __shfl_xor_sync(0xffffffffu, sqB, 1);
      sA += __shfl_xor_sync(0xffffffffu, sA, 2);  sqA += __shfl_xor_sync(0xffffffffu, sqA, 2);
      sB += __shfl_xor_sync(0xffffffffu, sB, 2);  sqB += __shfl_xor_sync(0xffffffffu, sqB, 2);
      float mA = sA*(1.f/32.f), vA = sqA*(1.f/32.f) - mA*mA;
      float mB = sB*(1.f/32.f), vB = sqB*(1.f/32.f) - mB*mB;
      float rA2 = rsqrtf(vA + 1e-5f), rB2 = rsqrtf(vB + 1e-5f);
      float wv = g_wmix[(l*CC + c)*NOPS + o];
      #pragma unroll
      for (int fi=0; fi<4; fi++){
        int f = 4*ch + fi;
        int col0 = wc*64 + f*8 + 2*tig;
        float lg0=s_lg[col0], lg1=s_lg[col0+1], lb0=s_lb[col0], lb1=s_lb[col0+1];
        mix[f][0] += wv*((tv[fi][0]-mA)*rA2*lg0 + lb0);
        mix[f][1] += wv*((tv[fi][1]-mA)*rA2*lg1 + lb1);
        mix[f][2] += wv*((tv[fi][2]-mB)*rB2*lg0 + lb0);
        mix[f][3] += wv*((tv[fi][3]-mB)*rB2*lg1 + lb1);
      }
    }
  }
  int rA = n0 + wr*16 + g;
  int rB = rA + 8;
  float* yout = g_gr + (size_t)(l+1)*NN*HH;
  #pragma unroll
  for (int f=0; f<8; f++){
    int col = wc*64 + f*8 + 2*tig;
    if (rA < NN) *(float2*)&yout[(size_t)rA*HH + col] = make_float2(mix[f][0], mix[f][1]);
    if (rB < NN) *(float2*)&yout[(size_t)rB*HH + col] = make_float2(mix[f][2], mix[f][3]);
  }
}

// ------------------------- BatchNorm stats (standalone, fused finisher) -------------------------
__global__ void k_bnstat(const float* __restrict__ bng, const float* __restrict__ bnb, int l){
  int t = threadIdx.x; int b = blockIdx.x;
  const float* y = g_gr + (size_t)(l+1)*NN*HH;
  float s=0.f, sq=0.f;
  for (int r=b; r<NN; r+=BNG){
    float v = y[(size_t)r*HH + t];
    s+=v; sq+=v*v;
  }
  g_part[b*HH+t]=s;
  g_part[BNG*HH + b*HH+t]=sq;
  __threadfence();
  __shared__ int lastS;
  if (t==0) lastS = (atomicAdd(&g_cbn,1) == BNG-1);
  __syncthreads();
  if (lastS){
    float ts=0.f, tq=0.f;
    for (int bb=0;bb<BNG;bb++){ ts+=g_part[bb*HH+t]; tq+=g_part[BNG*HH+bb*HH+t]; }
    float mean = ts*(1.f/NN);
    float var  = tq*(1.f/NN) - mean*mean;
    float sc = bng[l*HH+t]*rsqrtf(var+1e-5f);
    g_scA[(l+1)*HH+t] = sc;
    g_shA[(l+1)*HH+t] = bnb[l*HH+t]-mean*sc;
    if (t==0) g_cbn = 0;
  }
}

// ------------------------- virtual node MLP (vt fused into vnl1) -------------------------
__global__ void k_vnl1(const float* __restrict__ vn0,
                       const float* __restrict__ W1, const float* __restrict__ b1,
                       const float* __restrict__ bn_g, const float* __restrict__ bn_b, int l){
  __shared__ float vp[2][HH];
  __shared__ float vr[HH];
  __shared__ int lastS;
  int row=blockIdx.x, t=threadIdx.x;
  int s=g_bstart[row], e=g_bstart[row+1];
  {
    int half = t>>7, col = t&127;
    float acc=0.f;
    const float* gp = g_gr + (size_t)(l+1)*NN*HH;
    for (int r=s+half; r<e; r+=2) acc += gp[(size_t)r*HH+col];
    vp[half][col]=acc;
  }
  __syncthreads();
  if (t < HH){
    float sc = g_scA[(l+1)*HH+t], sh = g_shA[(l+1)*HH+t];
    float acc = (vp[0][t]+vp[1][t])*sc + (float)(e-s)*sh;
    float vnv;
    if (l == 0) vnv = vn0[t];
    else { float v = g_h2[row*HH+t]*g_sc2[t]+g_sh2[t]; vnv = v>0.f? v:0.f; }
    vr[t] = acc + vnv;
  }
  __syncthreads();
  float acc = b1[l*2*HH+t];
  const float* wp = W1 + (size_t)l*HH*2*HH + t;
  #pragma unroll 4
  for (int h=0;h<HH;h++) acc += vr[h]*wp[h*2*HH];
  g_h1[row*2*HH+t]=acc;
  __threadfence();
  if (t==0) lastS = (atomicAdd(&g_c1,1) == NB-1);
  __syncthreads();
  if (lastS){
    float s2=0.f, sq=0.f;
    for (int r=0;r<NB;r++){ float v=g_h1[r*2*HH+t]; s2+=v; sq+=v*v; }
    float mean=s2*(1.f/NB);
    float var=sq*(1.f/NB)-mean*mean;
    float sc = bn_g[l*2*HH+t]*rsqrtf(var+1e-5f);
    g_sc1[t]=sc;
    g_sh1[t]=bn_b[l*2*HH+t]-mean*sc;
    if (t==0) g_c1 = 0;
  }
}
__global__ void k_vnl2(const float* __restrict__ W2, const float* __restrict__ b2,
                       const float* __restrict__ bn_g, const float* __restrict__ bn_b, int l){
  __shared__ float hr[2*HH];
  __shared__ int lastS;
  int row=blockIdx.x, t=threadIdx.x;
  {
    float v0 = g_h1[row*2*HH+t]*g_sc1[t]+g_sh1[t];
    float v1 = g_h1[row*2*HH+t+HH]*g_sc1[t+HH]+g_sh1[t+HH];
    hr[t]    = v0>0.f? v0:0.f;
    hr[t+HH] = v1>0.f? v1:0.f;
  }
  __syncthreads();
  float acc = b2[l*HH+t];
  const float* wp = W2 + (size_t)l*2*HH*HH + t;
  #pragma unroll 4
  for (int h=0;h<2*HH;h++) acc += hr[h]*wp[h*HH];
  g_h2[row*HH+t]=acc;
  __threadfence();
  if (t==0) lastS = (atomicAdd(&g_c2,1) == NB-1);
  __syncthreads();
  if (lastS){
    float s=0.f, sq=0.f;
    for (int r=0;r<NB;r++){ float v=g_h2[r*HH+t]; s+=v; sq+=v*v; }
    float mean=s*(1.f/NB);
    float var=sq*(1.f/NB)-mean*mean;
    float sc = bn_g[l*HH+t]*rsqrtf(var+1e-5f);
    g_sc2[t]=sc;
    g_sh2[t]=bn_b[l*HH+t]-mean*sc;
    if (t==0) g_c2 = 0;
  }
}

// ------------------------- pooling + head (stage-parallel pool) -------------------------
__global__ void k_pool(){
  int b=blockIdx.x, st=blockIdx.y, t=threadIdx.x;
  int s=g_bstart[b], e=g_bstart[b+1];
  float inv = 1.f/(float)max(e-s,1);
  const float* gp = g_gr + (size_t)st*NN*HH;
  float sc = g_scA[st*HH+t], sh = g_shA[st*HH+t];
  float sum=0.f, mx=-1e30f;
  for (int r=s;r<e;r++){
    float v=gp[(size_t)r*HH+t]*sc+sh;
    sum+=v; mx=fmaxf(mx,v);
  }
  if (e==s) mx=0.f;
  g_pooled[b*1024 + st*HH + t] = sum*inv;
  g_pooled[b*1024 + 512 + st*HH + t] = mx;
}
__global__ void k_head(const float* __restrict__ hW, const float* __restrict__ hb,
                       const float* __restrict__ hM, float* __restrict__ out){
  __shared__ float red[NOUT];
  int b=blockIdx.x, t=threadIdx.x;
  if (t<NOUT) red[t]=0.f;
  __syncthreads();
  float acc[NOUT];
  #pragma unroll
  for (int j=0;j<NOUT;j++) acc[j]=0.f;
  for (int d=t; d<1024; d+=256){
    float pv = g_pooled[b*1024+d];
    const float* wrow = hW + d*NOUT;
    const float* mrow = hM + d*NOUT;
    #pragma unroll
    for (int j=0;j<NOUT;j++) acc[j] += pv*wrow[j]*mrow[j];
  }
  #pragma unroll
  for (int j=0;j<NOUT;j++) atomicAdd(&red[j], acc[j]);
  __syncthreads();
  if (t<NOUT) out[b*NOUT+t] = red[t] + hb[t];
}

// ------------------------- launch -------------------------
extern "C" void kernel_launch(void* const* d_in, const int* in_sizes, int n_in,
                              void* d_out, int out_size){
  const float* x      = (const float*)d_in[0];
  const int*   ei     = (const int*)d_in[1];
  const int*   batch  = (const int*)d_in[2];
  const float* lin1W  = (const float*)d_in[3];
  const float* lin1b  = (const float*)d_in[4];
  const float* vn0    = (const float*)d_in[5];
  const float* Wops   = (const float*)d_in[6];
  const float* bops   = (const float*)d_in[7];
  const float* atta   = (const float*)d_in[8];
  const float* lng    = (const float*)d_in[9];
  const float* lnb    = (const float*)d_in[10];
  const float* bng    = (const float*)d_in[11];
  const float* bnb    = (const float*)d_in[12];
  const float* vnW1   = (const float*)d_in[13];
  const float* vnb1   = (const float*)d_in[14];
  const float* vnbn1g = (const float*)d_in[15];
  const float* vnbn1b = (const float*)d_in[16];
  const float* vnW2   = (const float*)d_in[17];
  const float* vnb2   = (const float*)d_in[18];
  const float* vnbn2g = (const float*)d_in[19];
  const float* vnbn2b = (const float*)d_in[20];
  const float* alphas = (const float*)d_in[21];
  const float* headW  = (const float*)d_in[22];
  const float* headb  = (const float*)d_in[23];
  const float* headM  = (const float*)d_in[24];
  float* out = (float*)d_out;
  const int* src = ei;
  const int* dst = ei + NE;

  cudaFuncSetAttribute(k_mix_mma, cudaFuncAttributeMaxDynamicSharedMemorySize, SMEM_MIX);
  cudaFuncSetAttribute(k_lin1_mma, cudaFuncAttributeMaxDynamicSharedMemorySize, SMEM_L1);

  const int NBLK = (NN + 255)/256;
  const int WBLK = (NN*32 + 255)/256;
  const int EBLK = (NE + 255)/256;
  const int MIXBLK = (NN + MT-1)/MT;   // 782

  k_zero_deg<<<NBLK,256>>>();
  k_count<<<EBLK,256>>>(dst);
  k_scan<<<1,1024>>>();
  k_wprep1<<<(128*64+255)/256,256>>>(lin1W);
  k_wprep<<<(LL*NOPS*16384+255)/256,256>>>(Wops);
  k_lin1_mma<<<MIXBLK,256,SMEM_L1>>>(x, lin1b);
  k_scatter<<<EBLK,256>>>(src, dst);
  k_bstart<<<NBLK,256>>>(batch);
  k_prepw<<<1,128>>>(alphas);

  for (int l=0; l<LL; l++){
    k_nodeA<<<WBLK,256>>>(batch, atta, vn0, l);
    k_edge<<<WBLK,256>>>();
    k_mix_mma<<<MIXBLK,256,SMEM_MIX>>>(l, bops, lng, lnb);
    k_bnstat<<<BNG,128>>>(bng, bnb, l);
    if (l < LL-1){
      k_vnl1<<<NB,256>>>(vn0, vnW1, vnb1, vnbn1g, vnbn1b, l);
      k_vnl2<<<NB,128>>>(vnW2, vnb2, vnbn2g, vnbn2b, l);
    }
  }
  k_pool<<<dim3(NB,4),128>>>();
  k_head<<<NB,256>>>(headW, headb, headM, out);
}

// round 17
// speedup vs baseline: 1.1107x; 1.0071x over previous
#include <cuda_runtime.h>
#include <cuda_bf16.h>
#include <math.h>
#include <stdint.h>

#define NN 50000
#define NE 800000
#define FIN 64
#define HH 128
#define LL 3
#define CC 4
#define KK 32
#define NOPS 7
#define NB 512
#define NOUT 10
#define BNG 400

// ------------------------- device scratch (no allocs) -------------------------
__device__ float g_gr[(LL+1)*NN*HH];
__device__ float g_xw[NN*HH];
__device__ float g_sum[NN*HH];
__device__ float g_nrm[NN*HH];
__device__ float g_att[NN*HH];
__device__ float g_s0[NN];
__device__ float g_s1[NN];
__device__ float g_dinv[NN];
__device__ float g_minv[NN];
__device__ int   g_deg[NN];
__device__ int   g_rowptr[NN+1];
__device__ int   g_cursor[NN];
__device__ int   g_csrsrc[NE];
__device__ int   g_bstart[NB+1];
__device__ float g_wmix[LL*CC*NOPS];
__device__ float g_h1[NB*2*HH];
__device__ float g_h2[NB*HH];
__device__ float g_scA[(LL+1)*HH];
__device__ float g_shA[(LL+1)*HH];
__device__ float g_sc1[2*HH];
__device__ float g_sh1[2*HH];
__device__ float g_sc2[HH];
__device__ float g_sh2[HH];
__device__ float g_part[2*BNG*HH];
__device__ float g_pooled[NB*8*HH];
__device__ int   g_cbn = 0;
__device__ int   g_c1 = 0;
__device__ int   g_c2 = 0;
__device__ unsigned short g_Whi[LL*NOPS*16384];
__device__ unsigned short g_Wlo[LL*NOPS*16384];
__device__ unsigned short g_W1hi[128*64];
__device__ unsigned short g_W1lo[128*64];

// ------------------------- PTX helpers (baseline ISA, sm_80+) -------------------------
__device__ __forceinline__ uint32_t smem_u32(const void* p){
  uint32_t a; asm("{ .reg .u64 t; cvta.to.shared.u64 t, %1; cvt.u32.u64 %0, t; }" : "=r"(a) : "l"(p));
  return a;
}
__device__ __forceinline__ void ldsm4(uint32_t &r0, uint32_t &r1, uint32_t &r2, uint32_t &r3, uint32_t addr){
  asm volatile("ldmatrix.sync.aligned.m8n8.x4.shared.b16 {%0,%1,%2,%3}, [%4];"
    : "=r"(r0), "=r"(r1), "=r"(r2), "=r"(r3) : "r"(addr));
}
__device__ __forceinline__ void mma16816(float* d, const uint32_t* a, const uint32_t* b){
  asm volatile("mma.sync.aligned.m16n8k16.row.col.f32.bf16.bf16.f32 "
    "{%0,%1,%2,%3}, {%4,%5,%6,%7}, {%8,%9}, {%0,%1,%2,%3};"
    : "+f"(d[0]), "+f"(d[1]), "+f"(d[2]), "+f"(d[3])
    : "r"(a[0]), "r"(a[1]), "r"(a[2]), "r"(a[3]), "r"(b[0]), "r"(b[1]));
}
__device__ __forceinline__ void cpa16(uint32_t saddr, const void* gaddr){
  asm volatile("cp.async.cg.shared.global [%0], [%1], 16;" :: "r"(saddr), "l"(gaddr));
}
#define CPA_COMMIT() asm volatile("cp.async.commit_group;" ::: "memory")
#define CPA_WAIT()   asm volatile("cp.async.wait_group 0;" ::: "memory")

// ------------------------- CSR build -------------------------
__global__ void k_zero_deg(){
  int i = blockIdx.x*blockDim.x + threadIdx.x;
  if (i < NN) g_deg[i] = 0;
}
__global__ void k_count(const int* __restrict__ dst){
  int e = blockIdx.x*blockDim.x + threadIdx.x;
  if (e < NE) atomicAdd(&g_deg[dst[e]], 1);
}
__global__ void k_scan(){
  __shared__ int sm[1024];
  const int CH = (NN + 1023)/1024;
  int t = threadIdx.x;
  int s = 0;
  for (int i=0;i<CH;i++){ int idx = t*CH+i; if (idx<NN) s += g_deg[idx]; }
  sm[t] = s; __syncthreads();
  for (int off=1; off<1024; off<<=1){
    int v = (t>=off) ? sm[t-off] : 0;
    __syncthreads();
    if (t>=off) sm[t] += v;
    __syncthreads();
  }
  int run = (t>0)? sm[t-1] : 0;
  for (int i=0;i<CH;i++){
    int idx=t*CH+i;
    if (idx<NN){
      g_rowptr[idx]=run;
      g_cursor[idx]=run;
      int d = g_deg[idx];
      run += d;
      float dc = (float)max(d, 1);
      g_dinv[idx] = rsqrtf(dc);
      g_minv[idx] = 1.f/dc;
    }
  }
  if (t==1023) g_rowptr[NN] = sm[1023];
}
__global__ void k_scatter(const int* __restrict__ src, const int* __restrict__ dst){
  int e = blockIdx.x*blockDim.x + threadIdx.x;
  if (e < NE){
    int slot = atomicAdd(&g_cursor[dst[e]], 1);
    g_csrsrc[slot] = src[e];
  }
}
__global__ void k_bstart(const int* __restrict__ batch){
  int i = blockIdx.x*blockDim.x + threadIdx.x;
  if (i >= NN) return;
  int b = batch[i];
  if (i == 0){ for (int bb=0; bb<=b; bb++) g_bstart[bb] = 0; }
  else { int p = batch[i-1]; for (int bb=p+1; bb<=b; bb++) g_bstart[bb] = i; }
  if (i == NN-1){ for (int bb=b+1; bb<=NB; bb++) g_bstart[bb] = NN; }
}
__global__ void k_prepw(const float* __restrict__ alphas){
  int g = threadIdx.x;
  if (g < 128){ g_scA[g] = 1.f; g_shA[g] = 0.f; }
  if (g < LL*CC){
    const float* a = alphas + g*NOPS;
    float mx = a[0];
    for (int o=1;o<NOPS;o++) mx = fmaxf(mx, a[o]);
    float e[NOPS]; float s = 0.f;
    for (int o=0;o<NOPS;o++){ e[o] = expf(a[o]-mx); s += e[o]; }
    for (int o=0;o<NOPS;o++) g_wmix[g*NOPS+o] = e[o]/s;
  }
}

// ------------------------- weight prep -------------------------
__global__ void k_wprep(const float* __restrict__ Wops){
  int idx = blockIdx.x*blockDim.x + threadIdx.x;
  if (idx >= LL*NOPS*16384) return;
  int lop = idx >> 14;
  int el  = idx & 16383;
  int l = lop / NOPS, o = lop % NOPS;
  int r = el >> 7;
  int h = el & 127;
  int c = r >> 5, k = r & 31;
  float w = Wops[(((size_t)(l*CC + c)*NOPS + o)*HH + h)*KK + k];
  __nv_bfloat16 hb = __float2bfloat16(w);
  float res = w - __bfloat162float(hb);
  __nv_bfloat16 lb = __float2bfloat16(res);
  g_Whi[(size_t)lop*16384 + r*128 + h] = __bfloat16_as_ushort(hb);
  g_Wlo[(size_t)lop*16384 + r*128 + h] = __bfloat16_as_ushort(lb);
}
__global__ void k_wprep1(const float* __restrict__ W){
  int idx = blockIdx.x*blockDim.x + threadIdx.x;
  if (idx >= 128*64) return;
  int r = idx >> 6, h = idx & 63;
  float w = W[h*128 + r];
  __nv_bfloat16 hb = __float2bfloat16(w);
  float res = w - __bfloat162float(hb);
  __nv_bfloat16 lb = __float2bfloat16(res);
  g_W1hi[r*64+h] = __bfloat16_as_ushort(hb);
  g_W1lo[r*64+h] = __bfloat16_as_ushort(lb);
}

// ------------------------- lin1 + ELU via warp MMA -------------------------
#define PADK1 72
#define L1_AHI 0
#define L1_ALO (64*PADK1*2)
#define L1_WHI (2*64*PADK1*2)
#define L1_WLO (L1_WHI + 128*PADK1*2)
#define L1_BB  (L1_WLO + 128*PADK1*2)
#define SMEM_L1 (L1_BB + 512)

__global__ void __launch_bounds__(256,3) k_lin1_mma(const float* __restrict__ x,
    const float* __restrict__ bias){
  extern __shared__ char smc[];
  uint32_t sbase = smem_u32(smc);
  float* s_b1 = (float*)(smc + L1_BB);
  int tid = threadIdx.x;
  int lane = tid & 31, w = tid >> 5;
  int wr = w & 3, wc = w >> 2;
  int g = lane >> 2, tig = lane & 3;
  int n0 = blockIdx.x * 64;
  if (tid < 128) s_b1[tid] = bias[tid];

  #pragma unroll 1
  for (int it=0; it<8; it++){
    int wi = it*256 + tid;
    int r = wi >> 5;
    int h0 = (wi & 31)*2;
    int n = n0 + r;
    float vx=0.f, vy=0.f;
    if (n < NN){
      float2 a = *(const float2*)(x + (size_t)n*FIN + h0);
      vx=a.x; vy=a.y;
    }
    __nv_bfloat16 hx = __float2bfloat16(vx);
    __nv_bfloat16 hy = __float2bfloat16(vy);
    __nv_bfloat16 lx = __float2bfloat16(vx - __bfloat162float(hx));
    __nv_bfloat16 ly = __float2bfloat16(vy - __bfloat162float(hy));
    uint32_t off = (uint32_t)(r*PADK1 + h0)*2;
    *(uint32_t*)(smc + L1_AHI + off) = (uint32_t)__bfloat16_as_ushort(hx) | ((uint32_t)__bfloat16_as_ushort(hy)<<16);
    *(uint32_t*)(smc + L1_ALO + off) = (uint32_t)__bfloat16_as_ushort(lx) | ((uint32_t)__bfloat16_as_ushort(ly)<<16);
  }
  {
    const uint4* srcH = (const uint4*)g_W1hi;
    const uint4* srcL = (const uint4*)g_W1lo;
    #pragma unroll
    for (int it=0; it<4; it++){
      int i = it*256 + tid;
      int row = i >> 3, q = i & 7;
      uint32_t off = (uint32_t)(row*PADK1 + q*8)*2;
      *(uint4*)(smc + L1_WHI + off) = srcH[i];
      *(uint4*)(smc + L1_WLO + off) = srcL[i];
    }
  }
  __syncthreads();

  int a_off = ((lane&7) + ((lane>>3)&1)*8)*PADK1 + (lane>>4)*8;
  int b_off = (((lane>>4)&1)*8 + (lane&7))*PADK1 + ((lane>>3)&1)*8;
  uint32_t AbH = sbase + L1_AHI + (uint32_t)(wr*16*PADK1 + a_off)*2;
  uint32_t AbL = sbase + L1_ALO + (uint32_t)(wr*16*PADK1 + a_off)*2;
  uint32_t WbH = sbase + L1_WHI + (uint32_t)(wc*64*PADK1 + b_off)*2;
  uint32_t WbL = sbase + L1_WLO + (uint32_t)(wc*64*PADK1 + b_off)*2;

  float acc[8][4];
  #pragma unroll
  for (int f=0;f<8;f++){ acc[f][0]=0.f; acc[f][1]=0.f; acc[f][2]=0.f; acc[f][3]=0.f; }
  #pragma unroll
  for (int ks=0; ks<4; ks++){
    uint32_t k0b = (uint32_t)(ks*16)*2;
    uint32_t ah[4], al[4];
    ldsm4(ah[0],ah[1],ah[2],ah[3], AbH + k0b);
    ldsm4(al[0],al[1],al[2],al[3], AbL + k0b);
    #pragma unroll
    for (int nf=0; nf<4; nf++){
      uint32_t bh[4], bl[4];
      uint32_t woff = (uint32_t)(nf*16*PADK1)*2 + k0b;
      ldsm4(bh[0],bh[1],bh[2],bh[3], WbH + woff);
      ldsm4(bl[0],bl[1],bl[2],bl[3], WbL + woff);
      mma16816(acc[2*nf],   ah, bh);
      mma16816(acc[2*nf],   ah, bl);
      mma16816(acc[2*nf],   al, bh);
      mma16816(acc[2*nf+1], ah, bh+2);
      mma16816(acc[2*nf+1], ah, bl+2);
      mma16816(acc[2*nf+1], al, bh+2);
    }
  }
  int rA = n0 + wr*16 + g;
  int rB = rA + 8;
  #pragma unroll
  for (int f=0; f<8; f++){
    int col = wc*64 + f*8 + 2*tig;
    float b0 = s_b1[col], b1 = s_b1[col+1];
    float t0 = acc[f][0]+b0, t1 = acc[f][1]+b1;
    float t2 = acc[f][2]+b0, t3 = acc[f][3]+b1;
    t0 = t0>0.f ? t0 : expm1f(t0);
    t1 = t1>0.f ? t1 : expm1f(t1);
    t2 = t2>0.f ? t2 : expm1f(t2);
    t3 = t3>0.f ? t3 : expm1f(t3);
    if (rA < NN) *(float2*)&g_gr[(size_t)rA*HH + col] = make_float2(t0, t1);
    if (rB < NN) *(float2*)&g_gr[(size_t)rB*HH + col] = make_float2(t2, t3);
  }
}

// ------------------------- per-layer node prep (lazy BN affine + lazy vn) -------------------------
__global__ void k_nodeA(const int* __restrict__ batch, const float* __restrict__ atta,
                        const float* __restrict__ vn0, int l){
  int w = (blockIdx.x*blockDim.x + threadIdx.x) >> 5;
  int lane = threadIdx.x & 31;
  if (w >= NN) return;
  int b = batch[w];
  float4 xv = ((const float4*)(g_gr + (size_t)l*NN*HH))[w*32 + lane];
  float4 sc = ((const float4*)(g_scA + l*HH))[lane];
  float4 sh = ((const float4*)(g_shA + l*HH))[lane];
  xv.x = xv.x*sc.x+sh.x; xv.y = xv.y*sc.y+sh.y; xv.z = xv.z*sc.z+sh.z; xv.w = xv.w*sc.w+sh.w;
  float4 vv;
  if (l == 0){
    vv = ((const float4*)vn0)[lane];
  } else {
    float4 h2 = ((const float4*)g_h2)[b*32 + lane];
    float4 c2 = ((const float4*)g_sc2)[lane];
    float4 d2 = ((const float4*)g_sh2)[lane];
    vv.x = fmaxf(h2.x*c2.x+d2.x, 0.f);
    vv.y = fmaxf(h2.y*c2.y+d2.y, 0.f);
    vv.z = fmaxf(h2.z*c2.z+d2.z, 0.f);
    vv.w = fmaxf(h2.w*c2.w+d2.w, 0.f);
  }
  xv.x += vv.x; xv.y += vv.y; xv.z += vv.z; xv.w += vv.w;
  ((float4*)g_xw)[w*32 + lane] = xv;
  float4 a0 = ((const float4*)(atta + l*2*HH))[lane];
  float4 a1 = ((const float4*)(atta + l*2*HH + HH))[lane];
  float s0 = xv.x*a0.x + xv.y*a0.y + xv.z*a0.z + xv.w*a0.w;
  float s1 = xv.x*a1.x + xv.y*a1.y + xv.z*a1.z + xv.w*a1.w;
  #pragma unroll
  for (int off=16; off; off>>=1){
    s0 += __shfl_xor_sync(0xffffffffu, s0, off);
    s1 += __shfl_xor_sync(0xffffffffu, s1, off);
  }
  if (lane==0){ g_s0[w]=s0; g_s1[w]=s1; }
}

// ------------------------- fused attention + aggregation (warp per node) -------------------------
__global__ void k_edge(){
  int w = (blockIdx.x*blockDim.x + threadIdx.x) >> 5;
  int lane = threadIdx.x & 31;
  if (w >= NN) return;
  int s = g_rowptr[w], e = g_rowptr[w+1];
  float s1v = g_s1[w];
  float dv = g_dinv[w];
  float ss = 0.f;
  for (int j=s+lane; j<e; j+=32){
    float ev = g_s0[g_csrsrc[j]] + s1v;
    ev = ev>0.f ? ev : 0.2f*ev;
    ss += __expf(ev);
  }
  #pragma unroll
  for (int off=16; off; off>>=1) ss += __shfl_xor_sync(0xffffffffu, ss, off);
  float sinv = 1.f/(ss + 1e-16f);
  float4 a_s = make_float4(0.f,0.f,0.f,0.f);
  float4 a_n = a_s, a_a = a_s;
  int j = s;
  for (; j+4<=e; j+=4){
    int sn0=g_csrsrc[j], sn1=g_csrsrc[j+1], sn2=g_csrsrc[j+2], sn3=g_csrsrc[j+3];
    float4 x0 = ((const float4*)g_xw)[sn0*32 + lane];
    float4 x1 = ((const float4*)g_xw)[sn1*32 + lane];
    float4 x2 = ((const float4*)g_xw)[sn2*32 + lane];
    float4 x3 = ((const float4*)g_xw)[sn3*32 + lane];
    float e0=g_s0[sn0]+s1v, e1=g_s0[sn1]+s1v, e2=g_s0[sn2]+s1v, e3=g_s0[sn3]+s1v;
    e0 = e0>0.f? e0:0.2f*e0; e1 = e1>0.f? e1:0.2f*e1;
    e2 = e2>0.f? e2:0.2f*e2; e3 = e3>0.f? e3:0.2f*e3;
    float c0=__expf(e0)*sinv, c1=__expf(e1)*sinv, c2=__expf(e2)*sinv, c3=__expf(e3)*sinv;
    float w0=g_dinv[sn0]*dv, w1=g_dinv[sn1]*dv, w2=g_dinv[sn2]*dv, w3=g_dinv[sn3]*dv;
    a_s.x+=x0.x+x1.x+x2.x+x3.x; a_s.y+=x0.y+x1.y+x2.y+x3.y;
    a_s.z+=x0.z+x1.z+x2.z+x3.z; a_s.w+=x0.w+x1.w+x2.w+x3.w;
    a_n.x+=w0*x0.x+w1*x1.x+w2*x2.x+w3*x3.x; a_n.y+=w0*x0.y+w1*x1.y+w2*x2.y+w3*x3.y;
    a_n.z+=w0*x0.z+w1*x1.z+w2*x2.z+w3*x3.z; a_n.w+=w0*x0.w+w1*x1.w+w2*x2.w+w3*x3.w;
    a_a.x+=c0*x0.x+c1*x1.x+c2*x2.x+c3*x3.x; a_a.y+=c0*x0.y+c1*x1.y+c2*x2.y+c3*x3.y;
    a_a.z+=c0*x0.z+c1*x1.z+c2*x2.z+c3*x3.z; a_a.w+=c0*x0.w+c1*x1.w+c2*x2.w+c3*x3.w;
  }
  for (; j<e; j++){
    int sn = g_csrsrc[j];
    float ev = g_s0[sn] + s1v;
    ev = ev>0.f ? ev : 0.2f*ev;
    float ca = __expf(ev) * sinv;
    float nw = g_dinv[sn]*dv;
    float4 xv = ((const float4*)g_xw)[sn*32 + lane];
    a_s.x+=xv.x;      a_s.y+=xv.y;      a_s.z+=xv.z;      a_s.w+=xv.w;
    a_n.x+=nw*xv.x;   a_n.y+=nw*xv.y;   a_n.z+=nw*xv.z;   a_n.w+=nw*xv.w;
    a_a.x+=ca*xv.x;   a_a.y+=ca*xv.y;   a_a.z+=ca*xv.z;   a_a.w+=ca*xv.w;
  }
  ((float4*)g_sum)[w*32+lane]=a_s;
  ((float4*)g_nrm)[w*32+lane]=a_n;
  ((float4*)g_att)[w*32+lane]=a_a;
}

// ------------------------- warp-MMA mixed-op GEMM + LN + DARTS mix -------------------------
#define MT 64
#define PADK 136
#define SM_AHI 0
#define SM_ALO (MT*PADK*2)
#define SM_WHI (2*MT*PADK*2)
#define SM_WLO (SM_WHI + 128*PADK*2)
#define SM_BB  (SM_WLO + 128*PADK*2)
#define SM_LG  (SM_BB+512)
#define SM_LB  (SM_LG+512)
#define SMEM_MIX (SM_LB+512)

__constant__ int c_opseq[7] = {0,5,1,2,3,4,6};
__constant__ int c_asel[7]  = {0,0,1,2,3,4,5};

__global__ void __launch_bounds__(256,2) k_mix_mma(int l,
    const float* __restrict__ bops, const float* __restrict__ lng, const float* __restrict__ lnb){
  extern __shared__ char smc[];
  uint32_t sbase = smem_u32(smc);
  float* s_bb = (float*)(smc + SM_BB);
  float* s_lg = (float*)(smc + SM_LG);
  float* s_lb = (float*)(smc + SM_LB);
  int tid = threadIdx.x;
  int lane = tid & 31, w = tid >> 5;
  int wr = w & 3, wc = w >> 2;
  int g = lane >> 2, tig = lane & 3;
  int n0 = blockIdx.x * MT;
  if (tid < 128){ s_lg[tid] = lng[l*128+tid]; s_lb[tid] = lnb[l*128+tid]; }

  int a_off = ((lane&7) + ((lane>>3)&1)*8)*PADK + (lane>>4)*8;
  int b_off = (((lane>>4)&1)*8 + (lane&7))*PADK + ((lane>>3)&1)*8;
  uint32_t AbH = sbase + SM_AHI + (uint32_t)(wr*16*PADK + a_off)*2;
  uint32_t AbL = sbase + SM_ALO + (uint32_t)(wr*16*PADK + a_off)*2;
  uint32_t WbH = sbase + SM_WHI + (uint32_t)(wc*64*PADK)*2 + (uint32_t)b_off*2;
  uint32_t WbL = sbase + SM_WLO + (uint32_t)(wc*64*PADK)*2 + (uint32_t)b_off*2;

  float mix[8][4];
  #pragma unroll
  for (int f=0;f<8;f++){ mix[f][0]=0.f; mix[f][1]=0.f; mix[f][2]=0.f; mix[f][3]=0.f; }

  int prevA = -1;
  for (int oi=0; oi<7; oi++){
    int o = c_opseq[oi], asel = c_asel[oi];
    __syncthreads();
    // W tiles via cp.async — overlaps with A-build below
    {
      const uint4* srcH = (const uint4*)(g_Whi + (size_t)(l*NOPS+o)*16384);
      const uint4* srcL = (const uint4*)(g_Wlo + (size_t)(l*NOPS+o)*16384);
      #pragma unroll
      for (int it=0; it<8; it++){
        int i = it*256 + tid;
        int row = i >> 4, q = i & 15;
        uint32_t off = (uint32_t)(row*PADK + q*8)*2;
        cpa16(sbase + SM_WHI + off, srcH + i);
        cpa16(sbase + SM_WLO + off, srcL + i);
      }
      CPA_COMMIT();
    }
    if (asel != prevA){
      prevA = asel;
      #pragma unroll 4
      for (int it=0; it<16; it++){
        int wi = it*256 + tid;
        int r = wi >> 6;
        int h0 = (wi & 63)*2;
        int n = n0 + r;
        float vx=0.f, vy=0.f;
        if (n < NN){
          size_t base = (size_t)n*HH + h0;
          if (asel==0){ float2 a = *(const float2*)(g_nrm+base); vx=a.x; vy=a.y; }
          else if (asel==1){ float2 a=*(const float2*)(g_xw+base); float2 bq=*(const float2*)(g_sum+base); vx=a.x+bq.x; vy=a.y+bq.y; }
          else if (asel==2){ float2 a=*(const float2*)(g_att+base); vx=a.x; vy=a.y; }
          else if (asel==3){ float2 a=*(const float2*)(g_xw+base); float2 bq=*(const float2*)(g_sum+base); float m=g_minv[n]; vx=a.x+bq.x*m; vy=a.y+bq.y*m; }
          else if (asel==4){ float2 bq=*(const float2*)(g_sum+base); float m=g_minv[n]; vx=bq.x*m; vy=bq.y*m; }
          else { float2 a=*(const float2*)(g_xw+base); vx=a.x; vy=a.y; }
        }
        __nv_bfloat16 hx = __float2bfloat16(vx);
        __nv_bfloat16 hy = __float2bfloat16(vy);
        __nv_bfloat16 lx = __float2bfloat16(vx - __bfloat162float(hx));
        __nv_bfloat16 ly = __float2bfloat16(vy - __bfloat162float(hy));
        uint32_t off = (uint32_t)(r*PADK + h0)*2;
        *(uint32_t*)(smc + SM_AHI + off) = (uint32_t)__bfloat16_as_ushort(hx) | ((uint32_t)__bfloat16_as_ushort(hy)<<16);
        *(uint32_t*)(smc + SM_ALO + off) = (uint32_t)__bfloat16_as_ushort(lx) | ((uint32_t)__bfloat16_as_ushort(ly)<<16);
      }
    }
    if (tid < 128){
      int c = tid>>5, k = tid&31;
      s_bb[tid] = bops[((size_t)(l*CC + c)*NOPS + o)*KK + k];
    }
    CPA_WAIT();
    __syncthreads();

    float acc[8][4];
    #pragma unroll
    for (int f=0;f<8;f++){ acc[f][0]=0.f; acc[f][1]=0.f; acc[f][2]=0.f; acc[f][3]=0.f; }
    #pragma unroll 2
    for (int ks=0; ks<8; ks++){
      uint32_t k0b = (uint32_t)(ks*16)*2;
      uint32_t ah[4], al[4];
      ldsm4(ah[0],ah[1],ah[2],ah[3], AbH + k0b);
      ldsm4(al[0],al[1],al[2],al[3], AbL + k0b);
      #pragma unroll
      for (int nf=0; nf<4; nf++){
        uint32_t bh[4], bl[4];
        uint32_t woff = (uint32_t)(nf*16*PADK)*2 + k0b;
        ldsm4(bh[0],bh[1],bh[2],bh[3], WbH + woff);
        ldsm4(bl[0],bl[1],bl[2],bl[3], WbL + woff);
        mma16816(acc[2*nf],   ah, bh);
        mma16816(acc[2*nf],   ah, bl);
        mma16816(acc[2*nf],   al, bh);
        mma16816(acc[2*nf+1], ah, bh+2);
        mma16816(acc[2*nf+1], ah, bl+2);
        mma16816(acc[2*nf+1], al, bh+2);
      }
    }
    #pragma unroll
    for (int ch=0; ch<2; ch++){
      int c = wc*2 + ch;
      float tv[4][4];
      float sA=0.f, sqA=0.f, sB=0.f, sqB=0.f;
      #pragma unroll
      for (int fi=0; fi<4; fi++){
        int f = 4*ch + fi;
        int col0 = wc*64 + f*8 + 2*tig;
        float b0 = s_bb[col0], b1 = s_bb[col0+1];
        float t0 = acc[f][0]+b0, t1 = acc[f][1]+b1;
        float t2 = acc[f][2]+b0, t3 = acc[f][3]+b1;
        tv[fi][0]=t0; tv[fi][1]=t1; tv[fi][2]=t2; tv[fi][3]=t3;
        sA += t0+t1; sqA += t0*t0+t1*t1;
        sB += t2+t3; sqB += t2*t2+t3*t3;
      }
      sA += __shfl_xor_sync(0xffffffffu, sA, 1);  sqA += __shfl_xor_sync(0xffffffffu, sqA, 1);
      sB += __shfl_xor_sync(0xffffffffu, sB, 1);  sqB += __shfl_xor_sync(0xffffffffu, sqB, 1);
      sA += __shfl_xor_sync(0xffffffffu, sA, 2);  sqA += __shfl_xor_sync(0xffffffffu, sqA, 2);
      sB += __shfl_xor_sync(0xffffffffu, sB, 2);  sqB += __shfl_xor_sync(0xffffffffu, sqB, 2);
      float mA = sA*(1.f/32.f), vA = sqA*(1.f/32.f) - mA*mA;
      float mB = sB*(1.f/32.f), vB = sqB*(1.f/32.f) - mB*mB;
      float rA2 = rsqrtf(vA + 1e-5f), rB2 = rsqrtf(vB + 1e-5f);
      float wv = g_wmix[(l*CC + c)*NOPS + o];
      #pragma unroll
      for (int fi=0; fi<4; fi++){
        int f = 4*ch + fi;
        int col0 = wc*64 + f*8 + 2*tig;
        float lg0=s_lg[col0], lg1=s_lg[col0+1], lb0=s_lb[col0], lb1=s_lb[col0+1];
        mix[f][0] += wv*((tv[fi][0]-mA)*rA2*lg0 + lb0);
        mix[f][1] += wv*((tv[fi][1]-mA)*rA2*lg1 + lb1);
        mix[f][2] += wv*((tv[fi][2]-mB)*rB2*lg0 + lb0);
        mix[f][3] += wv*((tv[fi][3]-mB)*rB2*lg1 + lb1);
      }
    }
  }
  int rA = n0 + wr*16 + g;
  int rB = rA + 8;
  float* yout = g_gr + (size_t)(l+1)*NN*HH;
  #pragma unroll
  for (int f=0; f<8; f++){
    int col = wc*64 + f*8 + 2*tig;
    if (rA < NN) *(float2*)&yout[(size_t)rA*HH + col] = make_float2(mix[f][0], mix[f][1]);
    if (rB < NN) *(float2*)&yout[(size_t)rB*HH + col] = make_float2(mix[f][2], mix[f][3]);
  }
}

// ------------------------- BatchNorm stats (standalone, fused finisher) -------------------------
__global__ void k_bnstat(const float* __restrict__ bng, const float* __restrict__ bnb, int l){
  int t = threadIdx.x; int b = blockIdx.x;
  const float* y = g_gr + (size_t)(l+1)*NN*HH;
  float s=0.f, sq=0.f;
  for (int r=b; r<NN; r+=BNG){
    float v = y[(size_t)r*HH + t];
    s+=v; sq+=v*v;
  }
  g_part[b*HH+t]=s;
  g_part[BNG*HH + b*HH+t]=sq;
  __threadfence();
  __shared__ int lastS;
  if (t==0) lastS = (atomicAdd(&g_cbn,1) == BNG-1);
  __syncthreads();
  if (lastS){
    float ts=0.f, tq=0.f;
    for (int bb=0;bb<BNG;bb++){ ts+=g_part[bb*HH+t]; tq+=g_part[BNG*HH+bb*HH+t]; }
    float mean = ts*(1.f/NN);
    float var  = tq*(1.f/NN) - mean*mean;
    float sc = bng[l*HH+t]*rsqrtf(var+1e-5f);
    g_scA[(l+1)*HH+t] = sc;
    g_shA[(l+1)*HH+t] = bnb[l*HH+t]-mean*sc;
    if (t==0) g_cbn = 0;
  }
}

// ------------------------- virtual node MLP (vt fused into vnl1) -------------------------
__global__ void k_vnl1(const float* __restrict__ vn0,
                       const float* __restrict__ W1, const float* __restrict__ b1,
                       const float* __restrict__ bn_g, const float* __restrict__ bn_b, int l){
  __shared__ float vp[2][HH];
  __shared__ float vr[HH];
  __shared__ int lastS;
  int row=blockIdx.x, t=threadIdx.x;
  int s=g_bstart[row], e=g_bstart[row+1];
  {
    int half = t>>7, col = t&127;
    float acc=0.f;
    const float* gp = g_gr + (size_t)(l+1)*NN*HH;
    for (int r=s+half; r<e; r+=2) acc += gp[(size_t)r*HH+col];
    vp[half][col]=acc;
  }
  __syncthreads();
  if (t < HH){
    float sc = g_scA[(l+1)*HH+t], sh = g_shA[(l+1)*HH+t];
    float acc = (vp[0][t]+vp[1][t])*sc + (float)(e-s)*sh;
    float vnv;
    if (l == 0) vnv = vn0[t];
    else { float v = g_h2[row*HH+t]*g_sc2[t]+g_sh2[t]; vnv = v>0.f? v:0.f; }
    vr[t] = acc + vnv;
  }
  __syncthreads();
  float acc = b1[l*2*HH+t];
  const float* wp = W1 + (size_t)l*HH*2*HH + t;
  #pragma unroll 4
  for (int h=0;h<HH;h++) acc += vr[h]*wp[h*2*HH];
  g_h1[row*2*HH+t]=acc;
  __threadfence();
  if (t==0) lastS = (atomicAdd(&g_c1,1) == NB-1);
  __syncthreads();
  if (lastS){
    float s2=0.f, sq=0.f;
    for (int r=0;r<NB;r++){ float v=g_h1[r*2*HH+t]; s2+=v; sq+=v*v; }
    float mean=s2*(1.f/NB);
    float var=sq*(1.f/NB)-mean*mean;
    float sc = bn_g[l*2*HH+t]*rsqrtf(var+1e-5f);
    g_sc1[t]=sc;
    g_sh1[t]=bn_b[l*2*HH+t]-mean*sc;
    if (t==0) g_c1 = 0;
  }
}
__global__ void k_vnl2(const float* __restrict__ W2, const float* __restrict__ b2,
                       const float* __restrict__ bn_g, const float* __restrict__ bn_b, int l){
  __shared__ float hr[2*HH];
  __shared__ int lastS;
  int row=blockIdx.x, t=threadIdx.x;
  {
    float v0 = g_h1[row*2*HH+t]*g_sc1[t]+g_sh1[t];
    float v1 = g_h1[row*2*HH+t+HH]*g_sc1[t+HH]+g_sh1[t+HH];
    hr[t]    = v0>0.f? v0:0.f;
    hr[t+HH] = v1>0.f? v1:0.f;
  }
  __syncthreads();
  float acc = b2[l*HH+t];
  const float* wp = W2 + (size_t)l*2*HH*HH + t;
  #pragma unroll 4
  for (int h=0;h<2*HH;h++) acc += hr[h]*wp[h*HH];
  g_h2[row*HH+t]=acc;
  __threadfence();
  if (t==0) lastS = (atomicAdd(&g_c2,1) == NB-1);
  __syncthreads();
  if (lastS){
    float s=0.f, sq=0.f;
    for (int r=0;r<NB;r++){ float v=g_h2[r*HH+t]; s+=v; sq+=v*v; }
    float mean=s*(1.f/NB);
    float var=sq*(1.f/NB)-mean*mean;
    float sc = bn_g[l*HH+t]*rsqrtf(var+1e-5f);
    g_sc2[t]=sc;
    g_sh2[t]=bn_b[l*HH+t]-mean*sc;
    if (t==0) g_c2 = 0;
  }
}

// ------------------------- pooling + head (stage-parallel pool) -------------------------
__global__ void k_pool(){
  int b=blockIdx.x, st=blockIdx.y, t=threadIdx.x;
  int s=g_bstart[b], e=g_bstart[b+1];
  float inv = 1.f/(float)max(e-s,1);
  const float* gp = g_gr + (size_t)st*NN*HH;
  float sc = g_scA[st*HH+t], sh = g_shA[st*HH+t];
  float sum=0.f, mx=-1e30f;
  for (int r=s;r<e;r++){
    float v=gp[(size_t)r*HH+t]*sc+sh;
    sum+=v; mx=fmaxf(mx,v);
  }
  if (e==s) mx=0.f;
  g_pooled[b*1024 + st*HH + t] = sum*inv;
  g_pooled[b*1024 + 512 + st*HH + t] = mx;
}
__global__ void k_head(const float* __restrict__ hW, const float* __restrict__ hb,
                       const float* __restrict__ hM, float* __restrict__ out){
  __shared__ float red[NOUT];
  int b=blockIdx.x, t=threadIdx.x;
  if (t<NOUT) red[t]=0.f;
  __syncthreads();
  float acc[NOUT];
  #pragma unroll
  for (int j=0;j<NOUT;j++) acc[j]=0.f;
  for (int d=t; d<1024; d+=256){
    float pv = g_pooled[b*1024+d];
    const float* wrow = hW + d*NOUT;
    const float* mrow = hM + d*NOUT;
    #pragma unroll
    for (int j=0;j<NOUT;j++) acc[j] += pv*wrow[j]*mrow[j];
  }
  #pragma unroll
  for (int j=0;j<NOUT;j++) atomicAdd(&red[j], acc[j]);
  __syncthreads();
  if (t<NOUT) out[b*NOUT+t] = red[t] + hb[t];
}

// ------------------------- launch -------------------------
extern "C" void kernel_launch(void* const* d_in, const int* in_sizes, int n_in,
                              void* d_out, int out_size){
  const float* x      = (const float*)d_in[0];
  const int*   ei     = (const int*)d_in[1];
  const int*   batch  = (const int*)d_in[2];
  const float* lin1W  = (const float*)d_in[3];
  const float* lin1b  = (const float*)d_in[4];
  const float* vn0    = (const float*)d_in[5];
  const float* Wops   = (const float*)d_in[6];
  const float* bops   = (const float*)d_in[7];
  const float* atta   = (const float*)d_in[8];
  const float* lng    = (const float*)d_in[9];
  const float* lnb    = (const float*)d_in[10];
  const float* bng    = (const float*)d_in[11];
  const float* bnb    = (const float*)d_in[12];
  const float* vnW1   = (const float*)d_in[13];
  const float* vnb1   = (const float*)d_in[14];
  const float* vnbn1g = (const float*)d_in[15];
  const float* vnbn1b = (const float*)d_in[16];
  const float* vnW2   = (const float*)d_in[17];
  const float* vnb2   = (const float*)d_in[18];
  const float* vnbn2g = (const float*)d_in[19];
  const float* vnbn2b = (const float*)d_in[20];
  const float* alphas = (const float*)d_in[21];
  const float* headW  = (const float*)d_in[22];
  const float* headb  = (const float*)d_in[23];
  const float* headM  = (const float*)d_in[24];
  float* out = (float*)d_out;
  const int* src = ei;
  const int* dst = ei + NE;

  cudaFuncSetAttribute(k_mix_mma, cudaFuncAttributeMaxDynamicSharedMemorySize, SMEM_MIX);
  cudaFuncSetAttribute(k_lin1_mma, cudaFuncAttributeMaxDynamicSharedMemorySize, SMEM_L1);

  const int NBLK = (NN + 255)/256;
  const int WBLK = (NN*32 + 255)/256;
  const int EBLK = (NE + 255)/256;
  const int MIXBLK = (NN + MT-1)/MT;   // 782

  k_zero_deg<<<NBLK,256>>>();
  k_count<<<EBLK,256>>>(dst);
  k_scan<<<1,1024>>>();
  k_wprep1<<<(128*64+255)/256,256>>>(lin1W);
  k_wprep<<<(LL*NOPS*16384+255)/256,256>>>(Wops);
  k_lin1_mma<<<MIXBLK,256,SMEM_L1>>>(x, lin1b);
  k_scatter<<<EBLK,256>>>(src, dst);
  k_bstart<<<NBLK,256>>>(batch);
  k_prepw<<<1,128>>>(alphas);

  for (int l=0; l<LL; l++){
    k_nodeA<<<WBLK,256>>>(batch, atta, vn0, l);
    k_edge<<<WBLK,256>>>();
    k_mix_mma<<<MIXBLK,256,SMEM_MIX>>>(l, bops, lng, lnb);
    k_bnstat<<<BNG,128>>>(bng, bnb, l);
    if (l < LL-1){
      k_vnl1<<<NB,256>>>(vn0, vnW1, vnb1, vnbn1g, vnbn1b, l);
      k_vnl2<<<NB,128>>>(vnW2, vnb2, vnbn2g, vnbn2b, l);
    }
  }
  k_pool<<<dim3(NB,4),128>>>();
  k_head<<<NB,256>>>(headW, headb, headM, out);
}